// round 1
// baseline (speedup 1.0000x reference)
#include <cuda_runtime.h>
#include <cstdint>
#include <cstddef>

// ---------------- problem constants ----------------
#define BATCH 8
#define SEQ   1025
#define CH    3200
#define NH    25
#define HD    128
#define MROWS (BATCH*SEQ)   // 8200
#define EPS   1e-6f

// ---------------- device scratch (no allocation allowed) ----------------
__device__ float g_xr  [MROWS*CH];      // tf32-rounded x
__device__ float g_wqkv[CH*3*CH];       // tf32-rounded qkv weights
__device__ float g_wproj[CH*CH];        // tf32-rounded proj weights
__device__ float g_q   [MROWS*CH];
__device__ float g_k   [MROWS*CH];
__device__ float g_v   [MROWS*CH];
__device__ float g_o   [MROWS*CH];      // attention output (tf32-rounded)

// ---------------- PTX helpers ----------------
__device__ __forceinline__ unsigned f2tf(float x) {
    unsigned u;
    asm("cvt.rna.tf32.f32 %0, %1;" : "=r"(u) : "f"(x));
    return u;
}

__device__ __forceinline__ void mma_tf32(float c[4], const unsigned a[4], const unsigned b[2]) {
    asm volatile(
        "mma.sync.aligned.m16n8k8.row.col.f32.tf32.tf32.f32 "
        "{%0,%1,%2,%3}, {%4,%5,%6,%7}, {%8,%9}, {%0,%1,%2,%3};\n"
        : "+f"(c[0]), "+f"(c[1]), "+f"(c[2]), "+f"(c[3])
        : "r"(a[0]), "r"(a[1]), "r"(a[2]), "r"(a[3]), "r"(b[0]), "r"(b[1]));
}

__device__ __forceinline__ void cp_async16(unsigned smem_addr, const void* gptr, int srcBytes) {
    asm volatile("cp.async.cg.shared.global [%0], [%1], 16, %2;\n"
                 :: "r"(smem_addr), "l"(gptr), "r"(srcBytes) : "memory");
}
__device__ __forceinline__ void cp_commit() {
    asm volatile("cp.async.commit_group;\n" ::: "memory");
}
__device__ __forceinline__ void cp_wait1() {
    asm volatile("cp.async.wait_group 1;\n" ::: "memory");
}

// ---------------- tf32 pre-round ----------------
__global__ void tf32_round_kernel(const float* __restrict__ in, float* __restrict__ out, int n) {
    int i = blockIdx.x * blockDim.x + threadIdx.x;
    if (i < n) out[i] = __uint_as_float(f2tf(in[i]));
}

// ---------------- generic 128x128x32 TF32 GEMM ----------------
// C[M, Ndim] = A[M, K] @ B[K, Ndim] + bias, output row-stride is CH.
// split=1: column tile selects q/k/v buffer (Ndim = 3*CH), col within buffer = gcol % CH.
#define AS_STR 36
#define BS_STR 136
#define GEMM_SMEM ((2*128*AS_STR + 2*32*BS_STR) * 4)   // 71680 bytes

__global__ void gemm128(const float* __restrict__ A, const float* __restrict__ Bw,
                        const float* __restrict__ bias,
                        float* __restrict__ o0, float* __restrict__ o1, float* __restrict__ o2,
                        int Mdim, int Ndim, int Kdim, int split)
{
    extern __shared__ unsigned smem_g[];
    unsigned* As = smem_g;                    // [2][128][AS_STR]
    unsigned* Bs = smem_g + 2 * 128 * AS_STR; // [2][32][BS_STR]

    const int tid  = threadIdx.x;
    const int lane = tid & 31;
    const int wid  = tid >> 5;
    const int g    = lane >> 2;
    const int q    = lane & 3;
    const int m0   = blockIdx.x * 128;
    const int n0   = blockIdx.y * 128;
    const int wm   = (wid >> 2) * 64;   // warp M offset (2 rows of warps)
    const int wn   = (wid & 3) * 32;    // warp N offset (4 cols of warps)

    float c[4][4][4];
    #pragma unroll
    for (int i = 0; i < 4; i++)
        #pragma unroll
        for (int j = 0; j < 4; j++)
            #pragma unroll
            for (int t = 0; t < 4; t++) c[i][j][t] = 0.f;

    const int nk = Kdim >> 5;

    auto issue = [&](int kt, int buf) {
        const int k0 = kt << 5;
        unsigned* Ad = As + buf * 128 * AS_STR;
        unsigned* Bd = Bs + buf * 32 * BS_STR;
        #pragma unroll
        for (int i = 0; i < 4; i++) {
            int idx = tid + (i << 8);           // 0..1023 float4 units
            int r = idx >> 3, c4 = (idx & 7) << 2;
            int grow = m0 + r;
            const float* src = A + (size_t)(grow < Mdim ? grow : 0) * Kdim + k0 + c4;
            cp_async16((unsigned)__cvta_generic_to_shared(Ad + r * AS_STR + c4),
                       src, grow < Mdim ? 16 : 0);
        }
        #pragma unroll
        for (int i = 0; i < 4; i++) {
            int idx = tid + (i << 8);
            int r = idx >> 5, c4 = (idx & 31) << 2;
            const float* src = Bw + (size_t)(k0 + r) * Ndim + n0 + c4;
            cp_async16((unsigned)__cvta_generic_to_shared(Bd + r * BS_STR + c4), src, 16);
        }
    };

    issue(0, 0); cp_commit();
    if (nk > 1) issue(1, 1);
    cp_commit();

    for (int kt = 0; kt < nk; kt++) {
        cp_wait1();
        __syncthreads();
        const unsigned* Ab = As + (kt & 1) * 128 * AS_STR;
        const unsigned* Bb = Bs + (kt & 1) * 32 * BS_STR;
        #pragma unroll
        for (int ks = 0; ks < 4; ks++) {
            unsigned a[4][4], b[4][2];
            #pragma unroll
            for (int i = 0; i < 4; i++) {
                const unsigned* base = Ab + (wm + i * 16 + g) * AS_STR + ks * 8 + q;
                a[i][0] = base[0];
                a[i][1] = base[8 * AS_STR];
                a[i][2] = base[4];
                a[i][3] = base[8 * AS_STR + 4];
            }
            #pragma unroll
            for (int j = 0; j < 4; j++) {
                const unsigned* base = Bb + (ks * 8 + q) * BS_STR + wn + j * 8 + g;
                b[j][0] = base[0];
                b[j][1] = base[4 * BS_STR];
            }
            #pragma unroll
            for (int i = 0; i < 4; i++)
                #pragma unroll
                for (int j = 0; j < 4; j++)
                    mma_tf32(c[i][j], a[i], b[j]);
        }
        __syncthreads();
        if (kt + 2 < nk) issue(kt + 2, kt & 1);
        cp_commit();
    }

    // epilogue
    float* outp = o0;
    int colShift = 0;
    if (split) {
        int sel = n0 / CH;
        outp = (sel == 0) ? o0 : (sel == 1 ? o1 : o2);
        colShift = sel * CH;
    }
    #pragma unroll
    for (int i = 0; i < 4; i++) {
        int r0 = m0 + wm + i * 16 + g;
        #pragma unroll
        for (int j = 0; j < 4; j++) {
            int col = n0 + wn + j * 8 + 2 * q;
            float b0 = bias[col], b1 = bias[col + 1];
            if (r0 < Mdim) {
                float* d = outp + (size_t)r0 * CH + (col - colShift);
                d[0] = c[i][j][0] + b0;
                d[1] = c[i][j][1] + b1;
            }
            if (r0 + 8 < Mdim) {
                float* d = outp + (size_t)(r0 + 8) * CH + (col - colShift);
                d[0] = c[i][j][2] + b0;
                d[1] = c[i][j][3] + b1;
            }
        }
    }
}

// ---------------- RMSNorm over full C per row ----------------
__global__ void rmsnorm_kernel(float* __restrict__ qbuf, float* __restrict__ kbuf,
                               const float* __restrict__ qw, const float* __restrict__ kw)
{
    float* buf = blockIdx.y ? kbuf : qbuf;
    const float* w = blockIdx.y ? kw : qw;
    const size_t row = blockIdx.x;
    float4* p = (float4*)(buf + row * CH);
    const float4* wp = (const float4*)w;

    const int tid = threadIdx.x;
    float ss = 0.f;
    for (int i = tid; i < CH / 4; i += 256) {
        float4 v = p[i];
        ss += v.x * v.x + v.y * v.y + v.z * v.z + v.w * v.w;
    }
    __shared__ float red[8];
    #pragma unroll
    for (int off = 16; off > 0; off >>= 1) ss += __shfl_xor_sync(0xffffffffu, ss, off);
    if ((tid & 31) == 0) red[tid >> 5] = ss;
    __syncthreads();
    float tot = 0.f;
    #pragma unroll
    for (int i = 0; i < 8; i++) tot += red[i];
    const float rms = rsqrtf(tot * (1.f / CH) + EPS);

    for (int i = tid; i < CH / 4; i += 256) {
        float4 v = p[i];
        float4 wv = wp[i];
        v.x *= rms * wv.x; v.y *= rms * wv.y; v.z *= rms * wv.z; v.w *= rms * wv.w;
        p[i] = v;
    }
}

// ---------------- flash attention (online softmax, TF32 mma) ----------------
// Grid: (B*H, ceil(SEQ/128)). Block 256 (8 warps), each warp owns 16 q-rows.
#define QSTR 132
#define KSTR 132
#define VSTR 136
#define PSTR 68
#define ATTN_SMEM ((128*QSTR + 64*KSTR + 64*VSTR + 8*16*PSTR) * 4)   // 171008 bytes

__global__ void attn_kernel(const float* __restrict__ Q, const float* __restrict__ K,
                            const float* __restrict__ V, float* __restrict__ O)
{
    extern __shared__ unsigned sm[];
    unsigned* Qs = sm;                    // [128][QSTR]
    unsigned* Ks = Qs + 128 * QSTR;       // [64][KSTR]
    unsigned* Vs = Ks + 64 * KSTR;        // [64][VSTR]
    unsigned* Ps = Vs + 64 * VSTR;        // [8 warps][16][PSTR]

    const int tid  = threadIdx.x;
    const int lane = tid & 31;
    const int wid  = tid >> 5;
    const int g    = lane >> 2;
    const int q    = lane & 3;
    const int bh   = blockIdx.x;
    const int b    = bh / NH;
    const int h    = bh % NH;
    const int q0   = blockIdx.y * 128;
    const float scale = 0.08838834764831845f;   // 128^-0.5
    const size_t rowBase = (size_t)b * SEQ;

    // load Q tile (scaled, tf32-rounded)
    for (int i = tid; i < 128 * 32; i += 256) {
        int r = i >> 5, c4 = (i & 31) << 2;
        float4 v = make_float4(0.f, 0.f, 0.f, 0.f);
        int grow = q0 + r;
        if (grow < SEQ)
            v = *(const float4*)(Q + (rowBase + grow) * CH + h * HD + c4);
        unsigned* d = Qs + r * QSTR + c4;
        d[0] = f2tf(v.x * scale); d[1] = f2tf(v.y * scale);
        d[2] = f2tf(v.z * scale); d[3] = f2tf(v.w * scale);
    }

    float o[16][4];
    #pragma unroll
    for (int i = 0; i < 16; i++)
        #pragma unroll
        for (int t = 0; t < 4; t++) o[i][t] = 0.f;
    float mstat0 = -1e30f, mstat1 = -1e30f, lstat0 = 0.f, lstat1 = 0.f;

    const int nkt = (SEQ + 63) / 64;   // 17
    for (int kt = 0; kt < nkt; kt++) {
        __syncthreads();   // previous tile fully consumed (also orders Qs on kt=0)
        const int k0 = kt * 64;
        for (int i = tid; i < 64 * 32; i += 256) {
            int r = i >> 5, c4 = (i & 31) << 2;
            float4 kv = make_float4(0.f, 0.f, 0.f, 0.f);
            float4 vv = make_float4(0.f, 0.f, 0.f, 0.f);
            if (k0 + r < SEQ) {
                const size_t base = (rowBase + k0 + r) * CH + h * HD + c4;
                kv = *(const float4*)(K + base);
                vv = *(const float4*)(V + base);
            }
            unsigned* dk = Ks + r * KSTR + c4;
            dk[0] = f2tf(kv.x); dk[1] = f2tf(kv.y); dk[2] = f2tf(kv.z); dk[3] = f2tf(kv.w);
            unsigned* dv = Vs + r * VSTR + c4;
            dv[0] = f2tf(vv.x); dv[1] = f2tf(vv.y); dv[2] = f2tf(vv.z); dv[3] = f2tf(vv.w);
        }
        __syncthreads();

        // S = (Q*scale) @ K^T : warp tile 16x64
        float s[8][4];
        #pragma unroll
        for (int nt = 0; nt < 8; nt++)
            #pragma unroll
            for (int t = 0; t < 4; t++) s[nt][t] = 0.f;
        #pragma unroll
        for (int kb = 0; kb < 16; kb++) {
            unsigned a[4];
            const unsigned* qb = Qs + (wid * 16 + g) * QSTR + kb * 8 + q;
            a[0] = qb[0];
            a[1] = qb[8 * QSTR];
            a[2] = qb[4];
            a[3] = qb[8 * QSTR + 4];
            #pragma unroll
            for (int nt = 0; nt < 8; nt++) {
                const unsigned* kbp = Ks + (nt * 8 + g) * KSTR + kb * 8 + q;
                unsigned bb[2] = { kbp[0], kbp[4] };
                mma_tf32(s[nt], a, bb);
            }
        }

        // mask invalid key columns (last tile only)
        const int kvalid = SEQ - k0;
        if (kvalid < 64) {
            #pragma unroll
            for (int nt = 0; nt < 8; nt++) {
                int colb = nt * 8 + 2 * q;
                if (colb >= kvalid)     { s[nt][0] = -1e30f; s[nt][2] = -1e30f; }
                if (colb + 1 >= kvalid) { s[nt][1] = -1e30f; s[nt][3] = -1e30f; }
            }
        }

        // online softmax, write P (tf32) to warp-private smem
        unsigned* Pw = Ps + wid * 16 * PSTR;
        float al0, al1;
        {
            float cm = -1e30f;
            #pragma unroll
            for (int nt = 0; nt < 8; nt++) cm = fmaxf(cm, fmaxf(s[nt][0], s[nt][1]));
            cm = fmaxf(cm, __shfl_xor_sync(0xffffffffu, cm, 1));
            cm = fmaxf(cm, __shfl_xor_sync(0xffffffffu, cm, 2));
            float mn = fmaxf(mstat0, cm);
            al0 = __expf(mstat0 - mn);
            mstat0 = mn;
            float rs = 0.f;
            #pragma unroll
            for (int nt = 0; nt < 8; nt++) {
                float p0 = __expf(s[nt][0] - mn);
                float p1 = __expf(s[nt][1] - mn);
                rs += p0 + p1;
                Pw[g * PSTR + nt * 8 + 2 * q]     = f2tf(p0);
                Pw[g * PSTR + nt * 8 + 2 * q + 1] = f2tf(p1);
            }
            rs += __shfl_xor_sync(0xffffffffu, rs, 1);
            rs += __shfl_xor_sync(0xffffffffu, rs, 2);
            lstat0 = lstat0 * al0 + rs;
        }
        {
            float cm = -1e30f;
            #pragma unroll
            for (int nt = 0; nt < 8; nt++) cm = fmaxf(cm, fmaxf(s[nt][2], s[nt][3]));
            cm = fmaxf(cm, __shfl_xor_sync(0xffffffffu, cm, 1));
            cm = fmaxf(cm, __shfl_xor_sync(0xffffffffu, cm, 2));
            float mn = fmaxf(mstat1, cm);
            al1 = __expf(mstat1 - mn);
            mstat1 = mn;
            float rs = 0.f;
            #pragma unroll
            for (int nt = 0; nt < 8; nt++) {
                float p0 = __expf(s[nt][2] - mn);
                float p1 = __expf(s[nt][3] - mn);
                rs += p0 + p1;
                Pw[(g + 8) * PSTR + nt * 8 + 2 * q]     = f2tf(p0);
                Pw[(g + 8) * PSTR + nt * 8 + 2 * q + 1] = f2tf(p1);
            }
            rs += __shfl_xor_sync(0xffffffffu, rs, 1);
            rs += __shfl_xor_sync(0xffffffffu, rs, 2);
            lstat1 = lstat1 * al1 + rs;
        }
        #pragma unroll
        for (int nt2 = 0; nt2 < 16; nt2++) {
            o[nt2][0] *= al0; o[nt2][1] *= al0;
            o[nt2][2] *= al1; o[nt2][3] *= al1;
        }
        __syncwarp();

        // O += P @ V : warp tile 16x128 over k=64
        #pragma unroll
        for (int kb = 0; kb < 8; kb++) {
            unsigned a[4];
            const unsigned* pb = Pw + g * PSTR + kb * 8 + q;
            a[0] = pb[0];
            a[1] = pb[8 * PSTR];
            a[2] = pb[4];
            a[3] = pb[8 * PSTR + 4];
            #pragma unroll
            for (int nt2 = 0; nt2 < 16; nt2++) {
                const unsigned* vb = Vs + (kb * 8 + q) * VSTR + nt2 * 8 + g;
                unsigned bb[2] = { vb[0], vb[4 * VSTR] };
                mma_tf32(o[nt2], a, bb);
            }
        }
        // Ps reuse next iteration is protected by the loop-top __syncthreads
    }

    // write O (tf32-rounded so proj GEMM can consume directly)
    const float inv0 = 1.f / lstat0;
    const float inv1 = 1.f / lstat1;
    const int row0 = q0 + wid * 16 + g;
    #pragma unroll
    for (int nt2 = 0; nt2 < 16; nt2++) {
        int col = h * HD + nt2 * 8 + 2 * q;
        if (row0 < SEQ) {
            float* d = O + (rowBase + row0) * CH + col;
            d[0] = __uint_as_float(f2tf(o[nt2][0] * inv0));
            d[1] = __uint_as_float(f2tf(o[nt2][1] * inv0));
        }
        if (row0 + 8 < SEQ) {
            float* d = O + (rowBase + row0 + 8) * CH + col;
            d[0] = __uint_as_float(f2tf(o[nt2][2] * inv1));
            d[1] = __uint_as_float(f2tf(o[nt2][3] * inv1));
        }
    }
}

// ---------------- launch ----------------
extern "C" void kernel_launch(void* const* d_in, const int* in_sizes, int n_in,
                              void* d_out, int out_size)
{
    const float* x     = (const float*)d_in[0];
    const float* qkvW  = (const float*)d_in[1];
    const float* qkvB  = (const float*)d_in[2];
    const float* qNW   = (const float*)d_in[3];
    const float* kNW   = (const float*)d_in[4];
    const float* projW = (const float*)d_in[5];
    const float* projB = (const float*)d_in[6];
    float* out = (float*)d_out;

    float *pxr, *pwq, *pwp, *pq, *pk, *pv, *po;
    cudaGetSymbolAddress((void**)&pxr, g_xr);
    cudaGetSymbolAddress((void**)&pwq, g_wqkv);
    cudaGetSymbolAddress((void**)&pwp, g_wproj);
    cudaGetSymbolAddress((void**)&pq,  g_q);
    cudaGetSymbolAddress((void**)&pk,  g_k);
    cudaGetSymbolAddress((void**)&pv,  g_v);
    cudaGetSymbolAddress((void**)&po,  g_o);

    cudaFuncSetAttribute(gemm128,     cudaFuncAttributeMaxDynamicSharedMemorySize, GEMM_SMEM);
    cudaFuncSetAttribute(attn_kernel, cudaFuncAttributeMaxDynamicSharedMemorySize, ATTN_SMEM);

    const int n1 = MROWS * CH, n2 = CH * 3 * CH, n3 = CH * CH;
    tf32_round_kernel<<<(n1 + 255) / 256, 256>>>(x,     pxr, n1);
    tf32_round_kernel<<<(n2 + 255) / 256, 256>>>(qkvW,  pwq, n2);
    tf32_round_kernel<<<(n3 + 255) / 256, 256>>>(projW, pwp, n3);

    // qkv = x @ W_qkv + b (scattered into q/k/v buffers)
    gemm128<<<dim3(65, 75), 256, GEMM_SMEM>>>(pxr, pwq, qkvB, pq, pk, pv,
                                              MROWS, 3 * CH, CH, 1);
    // RMSNorm over full C for q and k
    rmsnorm_kernel<<<dim3(MROWS, 2), 256>>>(pq, pk, qNW, kNW);
    // flash attention
    attn_kernel<<<dim3(BATCH * NH, (SEQ + 127) / 128), 256, ATTN_SMEM>>>(pq, pk, pv, po);
    // out = attn_out @ W_proj + b
    gemm128<<<dim3(65, 25), 256, GEMM_SMEM>>>(po, pwp, projB, out, out, out,
                                              MROWS, CH, CH, 0);
}

// round 3
// speedup vs baseline: 1.5410x; 1.5410x over previous
#include <cuda_runtime.h>
#include <cuda_fp16.h>
#include <cstdint>
#include <cstddef>

// ---------------- problem constants ----------------
#define BATCH 8
#define SEQ   1025
#define CH    3200
#define NH    25
#define HD    128
#define MROWS (BATCH*SEQ)   // 8200
#define EPS   1e-6f

// ---------------- device scratch (no allocation allowed) ----------------
__device__ __half g_xh  [MROWS*CH];      // fp16 x
__device__ __half g_wqkvT[3*CH*CH];      // fp16, TRANSPOSED qkv weights [3C, C]
__device__ __half g_wprojT[CH*CH];       // fp16, TRANSPOSED proj weights [C, C]
__device__ float  g_q   [MROWS*CH];
__device__ float  g_k   [MROWS*CH];
__device__ float  g_v   [MROWS*CH];
__device__ __half g_o   [MROWS*CH];      // attention output (fp16 for proj GEMM)

// ---------------- PTX helpers ----------------
__device__ __forceinline__ unsigned f2tf(float x) {
    unsigned u;
    asm("cvt.rna.tf32.f32 %0, %1;" : "=r"(u) : "f"(x));
    return u;
}

__device__ __forceinline__ uint32_t smem_u32(const void* p) {
    uint32_t a;
    asm("{ .reg .u64 t; cvta.to.shared.u64 t, %1; cvt.u32.u64 %0, t; }" : "=r"(a) : "l"(p));
    return a;
}

__device__ __forceinline__ void cp_async16(uint32_t smem_addr, const void* gptr, int srcBytes) {
    asm volatile("cp.async.cg.shared.global [%0], [%1], 16, %2;\n"
                 :: "r"(smem_addr), "l"(gptr), "r"(srcBytes) : "memory");
}
__device__ __forceinline__ void cp_commit() {
    asm volatile("cp.async.commit_group;\n" ::: "memory");
}
__device__ __forceinline__ void cp_wait1() {
    asm volatile("cp.async.wait_group 1;\n" ::: "memory");
}

__device__ __forceinline__ void ldsm_x4(uint32_t r[4], uint32_t addr) {
    asm volatile("ldmatrix.sync.aligned.m8n8.x4.shared.b16 {%0,%1,%2,%3}, [%4];"
                 : "=r"(r[0]), "=r"(r[1]), "=r"(r[2]), "=r"(r[3]) : "r"(addr));
}

__device__ __forceinline__ void mma16816(float c[4], const uint32_t a[4],
                                         uint32_t b0, uint32_t b1) {
    asm volatile(
        "mma.sync.aligned.m16n8k16.row.col.f32.f16.f16.f32 "
        "{%0,%1,%2,%3}, {%4,%5,%6,%7}, {%8,%9}, {%0,%1,%2,%3};\n"
        : "+f"(c[0]), "+f"(c[1]), "+f"(c[2]), "+f"(c[3])
        : "r"(a[0]), "r"(a[1]), "r"(a[2]), "r"(a[3]), "r"(b0), "r"(b1));
}

// legacy tf32 mma for attention
__device__ __forceinline__ void mma_tf32(float c[4], const unsigned a[4], const unsigned b[2]) {
    asm volatile(
        "mma.sync.aligned.m16n8k8.row.col.f32.tf32.tf32.f32 "
        "{%0,%1,%2,%3}, {%4,%5,%6,%7}, {%8,%9}, {%0,%1,%2,%3};\n"
        : "+f"(c[0]), "+f"(c[1]), "+f"(c[2]), "+f"(c[3])
        : "r"(a[0]), "r"(a[1]), "r"(a[2]), "r"(a[3]), "r"(b[0]), "r"(b[1]));
}

#define SWZ(b) ((b) ^ (((b) >> 3) & 0x70))

// ---------------- prep kernels ----------------
__global__ void f2h_kernel(const float* __restrict__ in, __half* __restrict__ out, int n) {
    int i = blockIdx.x * blockDim.x + threadIdx.x;
    if (i < n) out[i] = __float2half_rn(in[i]);
}

// out[n][k] = half(in[k][n])
__global__ void transpose_h(const float* __restrict__ in, __half* __restrict__ out,
                            int K, int N) {
    __shared__ float t[32][33];
    const int nb = blockIdx.x * 32, kb = blockIdx.y * 32;
    const int tx = threadIdx.x, ty = threadIdx.y;
    #pragma unroll
    for (int j = 0; j < 32; j += 8)
        t[ty + j][tx] = in[(size_t)(kb + ty + j) * N + nb + tx];
    __syncthreads();
    #pragma unroll
    for (int j = 0; j < 32; j += 8)
        out[(size_t)(nb + ty + j) * K + kb + tx] = __float2half_rn(t[tx][ty + j]);
}

// ---------------- fp16 GEMM (ldmatrix + m16n8k16): C[M,*] = A @ BT^T + bias ----------------
// 128x128 tile per CTA, K-tile 64 halves (128B rows, SW128), 3-stage cp.async ring.
#define HSTG 32768                        // A(16KB) + B(16KB) per stage
#define HG_SMEM (3*HSTG)                  // 98304 bytes

__global__ void __launch_bounds__(256, 2) hgemm(
    const __half* __restrict__ A, const __half* __restrict__ BT,
    const float* __restrict__ bias,
    float* __restrict__ o0, float* __restrict__ o1, float* __restrict__ o2,
    int Mdim, int split)
{
    extern __shared__ char smg[];
    const uint32_t sb = smem_u32(smg);
    const int tid  = threadIdx.x;
    const int lane = tid & 31;
    const int wid  = tid >> 5;
    const int g    = lane >> 2;
    const int q    = lane & 3;
    const int m0   = blockIdx.x * 128;
    const int n0   = blockIdx.y * 128;
    const int wm   = (wid >> 2) * 64;
    const int wn   = (wid & 3) * 32;
    const int nk   = CH / 64;             // 50

    float c[4][4][4];
    #pragma unroll
    for (int i = 0; i < 4; i++)
        #pragma unroll
        for (int j = 0; j < 4; j++)
            #pragma unroll
            for (int t = 0; t < 4; t++) c[i][j][t] = 0.f;

    auto stage = [&](int ts) {
        const int k0 = ts * 64;
        const uint32_t bufb = sb + (ts % 3) * HSTG;
        #pragma unroll
        for (int i = 0; i < 4; i++) {            // A: 128 rows x 8 x 16B
            int idx = tid + (i << 8);
            int r = idx >> 3, ch = idx & 7;
            int grow = m0 + r;
            const __half* src = A + (size_t)(grow < Mdim ? grow : 0) * CH + k0 + ch * 8;
            uint32_t byte = (r << 7) + (ch << 4);
            cp_async16(bufb + SWZ(byte), src, grow < Mdim ? 16 : 0);
        }
        #pragma unroll
        for (int i = 0; i < 4; i++) {            // B: 128 n-rows x 8 x 16B (K-major)
            int idx = tid + (i << 8);
            int r = idx >> 3, ch = idx & 7;
            const __half* src = BT + (size_t)(n0 + r) * CH + k0 + ch * 8;
            uint32_t byte = (r << 7) + (ch << 4);
            cp_async16(bufb + 16384 + SWZ(byte), src, 16);
        }
        cp_commit();
    };

    stage(0);
    stage(1);

    // per-thread ldmatrix address roles
    const int aRow = wm + (lane & 15);           // + i*16
    const int aKb  = (lane >> 4) << 4;           // 0 or 16 bytes (k lo/hi half)
    const int bRow = wn + (lane & 7) + ((lane & 16) >> 1);   // + jj*16
    const int bKb  = (lane & 8) << 1;            // 0 or 16 bytes

    for (int kt = 0; kt < nk; kt++) {
        cp_wait1();
        __syncthreads();
        const uint32_t Ab = sb + (kt % 3) * HSTG;
        const uint32_t Bb = Ab + 16384;
        #pragma unroll
        for (int ks = 0; ks < 4; ks++) {
            uint32_t a[4][4], b[2][4];
            #pragma unroll
            for (int i = 0; i < 4; i++) {
                uint32_t byte = ((aRow + i * 16) << 7) + ks * 32 + aKb;
                ldsm_x4(a[i], Ab + SWZ(byte));
            }
            #pragma unroll
            for (int jj = 0; jj < 2; jj++) {
                uint32_t byte = ((bRow + jj * 16) << 7) + ks * 32 + bKb;
                ldsm_x4(b[jj], Bb + SWZ(byte));
            }
            #pragma unroll
            for (int i = 0; i < 4; i++) {
                mma16816(c[i][0], a[i], b[0][0], b[0][1]);
                mma16816(c[i][1], a[i], b[0][2], b[0][3]);
                mma16816(c[i][2], a[i], b[1][0], b[1][1]);
                mma16816(c[i][3], a[i], b[1][2], b[1][3]);
            }
        }
        __syncthreads();
        if (kt + 2 < nk) stage(kt + 2);
        else cp_commit();                 // keep group-count invariant
    }

    // epilogue
    float* outp = o0;
    int colShift = 0;
    if (split) {
        int sel = n0 / CH;
        outp = (sel == 0) ? o0 : (sel == 1 ? o1 : o2);
        colShift = sel * CH;
    }
    #pragma unroll
    for (int i = 0; i < 4; i++) {
        int r0 = m0 + wm + i * 16 + g;
        #pragma unroll
        for (int j = 0; j < 4; j++) {
            int col = n0 + wn + j * 8 + 2 * q;
            float b0 = bias[col], b1 = bias[col + 1];
            if (r0 < Mdim) {
                float* d = outp + (size_t)r0 * CH + (col - colShift);
                d[0] = c[i][j][0] + b0;
                d[1] = c[i][j][1] + b1;
            }
            if (r0 + 8 < Mdim) {
                float* d = outp + (size_t)(r0 + 8) * CH + (col - colShift);
                d[0] = c[i][j][2] + b0;
                d[1] = c[i][j][3] + b1;
            }
        }
    }
}

// ---------------- RMSNorm over full C per row ----------------
__global__ void rmsnorm_kernel(float* __restrict__ qbuf, float* __restrict__ kbuf,
                               const float* __restrict__ qw, const float* __restrict__ kw)
{
    float* buf = blockIdx.y ? kbuf : qbuf;
    const float* w = blockIdx.y ? kw : qw;
    const size_t row = blockIdx.x;
    float4* p = (float4*)(buf + row * CH);
    const float4* wp = (const float4*)w;

    const int tid = threadIdx.x;
    float ss = 0.f;
    for (int i = tid; i < CH / 4; i += 256) {
        float4 v = p[i];
        ss += v.x * v.x + v.y * v.y + v.z * v.z + v.w * v.w;
    }
    __shared__ float red[8];
    #pragma unroll
    for (int off = 16; off > 0; off >>= 1) ss += __shfl_xor_sync(0xffffffffu, ss, off);
    if ((tid & 31) == 0) red[tid >> 5] = ss;
    __syncthreads();
    float tot = 0.f;
    #pragma unroll
    for (int i = 0; i < 8; i++) tot += red[i];
    const float rms = rsqrtf(tot * (1.f / CH) + EPS);

    for (int i = tid; i < CH / 4; i += 256) {
        float4 v = p[i];
        float4 wv = wp[i];
        v.x *= rms * wv.x; v.y *= rms * wv.y; v.z *= rms * wv.z; v.w *= rms * wv.w;
        p[i] = v;
    }
}

// ---------------- flash attention (online softmax, TF32 mma.sync) ----------------
#define QSTR 132
#define KSTR 132
#define VSTR 136
#define PSTR 68
#define ATTN_SMEM ((128*QSTR + 64*KSTR + 64*VSTR + 8*16*PSTR) * 4)   // 171008 bytes

__global__ void attn_kernel(const float* __restrict__ Q, const float* __restrict__ K,
                            const float* __restrict__ V, __half* __restrict__ O)
{
    extern __shared__ unsigned sm[];
    unsigned* Qs = sm;
    unsigned* Ks = Qs + 128 * QSTR;
    unsigned* Vs = Ks + 64 * KSTR;
    unsigned* Ps = Vs + 64 * VSTR;

    const int tid  = threadIdx.x;
    const int lane = tid & 31;
    const int wid  = tid >> 5;
    const int g    = lane >> 2;
    const int q    = lane & 3;
    const int bh   = blockIdx.x;
    const int b    = bh / NH;
    const int h    = bh % NH;
    const int q0   = blockIdx.y * 128;
    const float scale = 0.08838834764831845f;
    const size_t rowBase = (size_t)b * SEQ;

    for (int i = tid; i < 128 * 32; i += 256) {
        int r = i >> 5, c4 = (i & 31) << 2;
        float4 v = make_float4(0.f, 0.f, 0.f, 0.f);
        int grow = q0 + r;
        if (grow < SEQ)
            v = *(const float4*)(Q + (rowBase + grow) * CH + h * HD + c4);
        unsigned* d = Qs + r * QSTR + c4;
        d[0] = f2tf(v.x * scale); d[1] = f2tf(v.y * scale);
        d[2] = f2tf(v.z * scale); d[3] = f2tf(v.w * scale);
    }

    float o[16][4];
    #pragma unroll
    for (int i = 0; i < 16; i++)
        #pragma unroll
        for (int t = 0; t < 4; t++) o[i][t] = 0.f;
    float mstat0 = -1e30f, mstat1 = -1e30f, lstat0 = 0.f, lstat1 = 0.f;

    const int nkt = (SEQ + 63) / 64;
    for (int kt = 0; kt < nkt; kt++) {
        __syncthreads();
        const int k0 = kt * 64;
        for (int i = tid; i < 64 * 32; i += 256) {
            int r = i >> 5, c4 = (i & 31) << 2;
            float4 kv = make_float4(0.f, 0.f, 0.f, 0.f);
            float4 vv = make_float4(0.f, 0.f, 0.f, 0.f);
            if (k0 + r < SEQ) {
                const size_t base = (rowBase + k0 + r) * CH + h * HD + c4;
                kv = *(const float4*)(K + base);
                vv = *(const float4*)(V + base);
            }
            unsigned* dk = Ks + r * KSTR + c4;
            dk[0] = f2tf(kv.x); dk[1] = f2tf(kv.y); dk[2] = f2tf(kv.z); dk[3] = f2tf(kv.w);
            unsigned* dv = Vs + r * VSTR + c4;
            dv[0] = f2tf(vv.x); dv[1] = f2tf(vv.y); dv[2] = f2tf(vv.z); dv[3] = f2tf(vv.w);
        }
        __syncthreads();

        float s[8][4];
        #pragma unroll
        for (int nt = 0; nt < 8; nt++)
            #pragma unroll
            for (int t = 0; t < 4; t++) s[nt][t] = 0.f;
        #pragma unroll
        for (int kb = 0; kb < 16; kb++) {
            unsigned a[4];
            const unsigned* qb = Qs + (wid * 16 + g) * QSTR + kb * 8 + q;
            a[0] = qb[0];
            a[1] = qb[8 * QSTR];
            a[2] = qb[4];
            a[3] = qb[8 * QSTR + 4];
            #pragma unroll
            for (int nt = 0; nt < 8; nt++) {
                const unsigned* kbp = Ks + (nt * 8 + g) * KSTR + kb * 8 + q;
                unsigned bb[2] = { kbp[0], kbp[4] };
                mma_tf32(s[nt], a, bb);
            }
        }

        const int kvalid = SEQ - k0;
        if (kvalid < 64) {
            #pragma unroll
            for (int nt = 0; nt < 8; nt++) {
                int colb = nt * 8 + 2 * q;
                if (colb >= kvalid)     { s[nt][0] = -1e30f; s[nt][2] = -1e30f; }
                if (colb + 1 >= kvalid) { s[nt][1] = -1e30f; s[nt][3] = -1e30f; }
            }
        }

        unsigned* Pw = Ps + wid * 16 * PSTR;
        float al0, al1;
        {
            float cm = -1e30f;
            #pragma unroll
            for (int nt = 0; nt < 8; nt++) cm = fmaxf(cm, fmaxf(s[nt][0], s[nt][1]));
            cm = fmaxf(cm, __shfl_xor_sync(0xffffffffu, cm, 1));
            cm = fmaxf(cm, __shfl_xor_sync(0xffffffffu, cm, 2));
            float mn = fmaxf(mstat0, cm);
            al0 = __expf(mstat0 - mn);
            mstat0 = mn;
            float rs = 0.f;
            #pragma unroll
            for (int nt = 0; nt < 8; nt++) {
                float p0 = __expf(s[nt][0] - mn);
                float p1 = __expf(s[nt][1] - mn);
                rs += p0 + p1;
                Pw[g * PSTR + nt * 8 + 2 * q]     = f2tf(p0);
                Pw[g * PSTR + nt * 8 + 2 * q + 1] = f2tf(p1);
            }
            rs += __shfl_xor_sync(0xffffffffu, rs, 1);
            rs += __shfl_xor_sync(0xffffffffu, rs, 2);
            lstat0 = lstat0 * al0 + rs;
        }
        {
            float cm = -1e30f;
            #pragma unroll
            for (int nt = 0; nt < 8; nt++) cm = fmaxf(cm, fmaxf(s[nt][2], s[nt][3]));
            cm = fmaxf(cm, __shfl_xor_sync(0xffffffffu, cm, 1));
            cm = fmaxf(cm, __shfl_xor_sync(0xffffffffu, cm, 2));
            float mn = fmaxf(mstat1, cm);
            al1 = __expf(mstat1 - mn);
            mstat1 = mn;
            float rs = 0.f;
            #pragma unroll
            for (int nt = 0; nt < 8; nt++) {
                float p0 = __expf(s[nt][2] - mn);
                float p1 = __expf(s[nt][3] - mn);
                rs += p0 + p1;
                Pw[(g + 8) * PSTR + nt * 8 + 2 * q]     = f2tf(p0);
                Pw[(g + 8) * PSTR + nt * 8 + 2 * q + 1] = f2tf(p1);
            }
            rs += __shfl_xor_sync(0xffffffffu, rs, 1);
            rs += __shfl_xor_sync(0xffffffffu, rs, 2);
            lstat1 = lstat1 * al1 + rs;
        }
        #pragma unroll
        for (int nt2 = 0; nt2 < 16; nt2++) {
            o[nt2][0] *= al0; o[nt2][1] *= al0;
            o[nt2][2] *= al1; o[nt2][3] *= al1;
        }
        __syncwarp();

        #pragma unroll
        for (int kb = 0; kb < 8; kb++) {
            unsigned a[4];
            const unsigned* pb = Pw + g * PSTR + kb * 8 + q;
            a[0] = pb[0];
            a[1] = pb[8 * PSTR];
            a[2] = pb[4];
            a[3] = pb[8 * PSTR + 4];
            #pragma unroll
            for (int nt2 = 0; nt2 < 16; nt2++) {
                const unsigned* vb = Vs + (kb * 8 + q) * VSTR + nt2 * 8 + g;
                unsigned bb[2] = { vb[0], vb[4 * VSTR] };
                mma_tf32(o[nt2], a, bb);
            }
        }
    }

    const float inv0 = 1.f / lstat0;
    const float inv1 = 1.f / lstat1;
    const int row0 = q0 + wid * 16 + g;
    #pragma unroll
    for (int nt2 = 0; nt2 < 16; nt2++) {
        int col = h * HD + nt2 * 8 + 2 * q;
        if (row0 < SEQ) {
            __half* d = O + (rowBase + row0) * CH + col;
            d[0] = __float2half_rn(o[nt2][0] * inv0);
            d[1] = __float2half_rn(o[nt2][1] * inv0);
        }
        if (row0 + 8 < SEQ) {
            __half* d = O + (rowBase + row0 + 8) * CH + col;
            d[0] = __float2half_rn(o[nt2][2] * inv1);
            d[1] = __float2half_rn(o[nt2][3] * inv1);
        }
    }
}

// ---------------- launch ----------------
extern "C" void kernel_launch(void* const* d_in, const int* in_sizes, int n_in,
                              void* d_out, int out_size)
{
    const float* x     = (const float*)d_in[0];
    const float* qkvW  = (const float*)d_in[1];
    const float* qkvB  = (const float*)d_in[2];
    const float* qNW   = (const float*)d_in[3];
    const float* kNW   = (const float*)d_in[4];
    const float* projW = (const float*)d_in[5];
    const float* projB = (const float*)d_in[6];
    float* out = (float*)d_out;

    __half *pxh, *pwqT, *pwpT, *po;
    float *pq, *pk, *pv;
    cudaGetSymbolAddress((void**)&pxh,  g_xh);
    cudaGetSymbolAddress((void**)&pwqT, g_wqkvT);
    cudaGetSymbolAddress((void**)&pwpT, g_wprojT);
    cudaGetSymbolAddress((void**)&pq,   g_q);
    cudaGetSymbolAddress((void**)&pk,   g_k);
    cudaGetSymbolAddress((void**)&pv,   g_v);
    cudaGetSymbolAddress((void**)&po,   g_o);

    cudaFuncSetAttribute(hgemm,       cudaFuncAttributeMaxDynamicSharedMemorySize, HG_SMEM);
    cudaFuncSetAttribute(attn_kernel, cudaFuncAttributeMaxDynamicSharedMemorySize, ATTN_SMEM);

    const int n1 = MROWS * CH;
    f2h_kernel<<<(n1 + 255) / 256, 256>>>(x, pxh, n1);
    // W_qkv [C, 3C] -> [3C, C] fp16 transposed
    transpose_h<<<dim3(3 * CH / 32, CH / 32), dim3(32, 8)>>>(qkvW, pwqT, CH, 3 * CH);
    // W_proj [C, C] -> [C, C] fp16 transposed
    transpose_h<<<dim3(CH / 32, CH / 32), dim3(32, 8)>>>(projW, pwpT, CH, CH);

    // qkv = x @ W_qkv + b (fp16 tensor cores, scattered into q/k/v buffers)
    hgemm<<<dim3(65, 75), 256, HG_SMEM>>>(pxh, pwqT, qkvB, pq, pk, pv, MROWS, 1);
    // RMSNorm over full C for q and k
    rmsnorm_kernel<<<dim3(MROWS, 2), 256>>>(pq, pk, qNW, kNW);
    // flash attention (tf32) -> fp16 output
    attn_kernel<<<dim3(BATCH * NH, (SEQ + 127) / 128), 256, ATTN_SMEM>>>(pq, pk, pv, po);
    // out = attn_out @ W_proj + b
    hgemm<<<dim3(65, 25), 256, HG_SMEM>>>(po, pwpT, projB, out, out, out, MROWS, 0);
}

// round 4
// speedup vs baseline: 3.1816x; 2.0647x over previous
#include <cuda_runtime.h>
#include <cuda_fp16.h>
#include <cstdint>
#include <cstddef>

// ---------------- problem constants ----------------
#define BATCH 8
#define SEQ   1025
#define CH    3200
#define NH    25
#define HD    128
#define MROWS (BATCH*SEQ)   // 8200
#define EPS   1e-6f
#define LOG2E 1.4426950408889634f

// ---------------- device scratch (no allocation allowed) ----------------
__device__ __half g_xh  [MROWS*CH];      // fp16 x
__device__ __half g_wqkvT[3*CH*CH];      // fp16, TRANSPOSED qkv weights [3C, C]
__device__ __half g_wprojT[CH*CH];       // fp16, TRANSPOSED proj weights [C, C]
__device__ float  g_q   [MROWS*CH];      // fp32 q (pre-norm)
__device__ float  g_k   [MROWS*CH];      // fp32 k (pre-norm)
__device__ __half g_qh  [MROWS*CH];      // fp16 normalized+scaled q
__device__ __half g_kh  [MROWS*CH];      // fp16 normalized k
__device__ __half g_vh  [MROWS*CH];      // fp16 v
__device__ __half g_o   [MROWS*CH];      // attention output (fp16 for proj GEMM)

// ---------------- PTX helpers ----------------
__device__ __forceinline__ uint32_t smem_u32(const void* p) {
    uint32_t a;
    asm("{ .reg .u64 t; cvta.to.shared.u64 t, %1; cvt.u32.u64 %0, t; }" : "=r"(a) : "l"(p));
    return a;
}

__device__ __forceinline__ void cp_async16(uint32_t smem_addr, const void* gptr, int srcBytes) {
    asm volatile("cp.async.cg.shared.global [%0], [%1], 16, %2;\n"
                 :: "r"(smem_addr), "l"(gptr), "r"(srcBytes) : "memory");
}
__device__ __forceinline__ void cp_commit() {
    asm volatile("cp.async.commit_group;\n" ::: "memory");
}
__device__ __forceinline__ void cp_wait1() {
    asm volatile("cp.async.wait_group 1;\n" ::: "memory");
}

__device__ __forceinline__ void ldsm_x4(uint32_t r[4], uint32_t addr) {
    asm volatile("ldmatrix.sync.aligned.m8n8.x4.shared.b16 {%0,%1,%2,%3}, [%4];"
                 : "=r"(r[0]), "=r"(r[1]), "=r"(r[2]), "=r"(r[3]) : "r"(addr));
}
__device__ __forceinline__ void ldsm_x4t(uint32_t r[4], uint32_t addr) {
    asm volatile("ldmatrix.sync.aligned.m8n8.x4.trans.shared.b16 {%0,%1,%2,%3}, [%4];"
                 : "=r"(r[0]), "=r"(r[1]), "=r"(r[2]), "=r"(r[3]) : "r"(addr));
}
__device__ __forceinline__ void ldsm_x2t(uint32_t r[2], uint32_t addr) {
    asm volatile("ldmatrix.sync.aligned.m8n8.x2.trans.shared.b16 {%0,%1}, [%2];"
                 : "=r"(r[0]), "=r"(r[1]) : "r"(addr));
}

__device__ __forceinline__ void mma16816(float c[4], const uint32_t a[4],
                                         uint32_t b0, uint32_t b1) {
    asm volatile(
        "mma.sync.aligned.m16n8k16.row.col.f32.f16.f16.f32 "
        "{%0,%1,%2,%3}, {%4,%5,%6,%7}, {%8,%9}, {%0,%1,%2,%3};\n"
        : "+f"(c[0]), "+f"(c[1]), "+f"(c[2]), "+f"(c[3])
        : "r"(a[0]), "r"(a[1]), "r"(a[2]), "r"(a[3]), "r"(b0), "r"(b1));
}

__device__ __forceinline__ uint32_t ex2_h2(uint32_t x) {
    uint32_t r;
    asm volatile("ex2.approx.f16x2 %0, %1;" : "=r"(r) : "r"(x));
    return r;
}

__device__ __forceinline__ uint32_t pack_h2(float lo, float hi) {
    __half2 h = __floats2half2_rn(lo, hi);
    return *reinterpret_cast<uint32_t*>(&h);
}

#define SWZ(b) ((b) ^ (((b) >> 3) & 0x70))

// ---------------- prep kernels ----------------
__global__ void f2h_kernel(const float* __restrict__ in, __half* __restrict__ out, int n) {
    int i = blockIdx.x * blockDim.x + threadIdx.x;
    if (i < n) out[i] = __float2half_rn(in[i]);
}

// out[n][k] = half(in[k][n])
__global__ void transpose_h(const float* __restrict__ in, __half* __restrict__ out,
                            int K, int N) {
    __shared__ float t[32][33];
    const int nb = blockIdx.x * 32, kb = blockIdx.y * 32;
    const int tx = threadIdx.x, ty = threadIdx.y;
    #pragma unroll
    for (int j = 0; j < 32; j += 8)
        t[ty + j][tx] = in[(size_t)(kb + ty + j) * N + nb + tx];
    __syncthreads();
    #pragma unroll
    for (int j = 0; j < 32; j += 8)
        out[(size_t)(nb + ty + j) * K + kb + tx] = __float2half_rn(t[tx][ty + j]);
}

// ---------------- fp16 GEMM (ldmatrix + m16n8k16): C[M,*] = A @ BT^T + bias ----------------
#define HSTG 32768
#define HG_SMEM (3*HSTG)

__global__ void __launch_bounds__(256, 2) hgemm(
    const __half* __restrict__ A, const __half* __restrict__ BT,
    const float* __restrict__ bias,
    float* __restrict__ oq, float* __restrict__ ok, __half* __restrict__ ov,
    float* __restrict__ od,
    int Mdim, int split)
{
    extern __shared__ char smg[];
    const uint32_t sb = smem_u32(smg);
    const int tid  = threadIdx.x;
    const int lane = tid & 31;
    const int wid  = tid >> 5;
    const int g    = lane >> 2;
    const int q    = lane & 3;
    const int m0   = blockIdx.x * 128;
    const int n0   = blockIdx.y * 128;
    const int wm   = (wid >> 2) * 64;
    const int wn   = (wid & 3) * 32;
    const int nk   = CH / 64;

    float c[4][4][4];
    #pragma unroll
    for (int i = 0; i < 4; i++)
        #pragma unroll
        for (int j = 0; j < 4; j++)
            #pragma unroll
            for (int t = 0; t < 4; t++) c[i][j][t] = 0.f;

    auto stage = [&](int ts) {
        const int k0 = ts * 64;
        const uint32_t bufb = sb + (ts % 3) * HSTG;
        #pragma unroll
        for (int i = 0; i < 4; i++) {
            int idx = tid + (i << 8);
            int r = idx >> 3, ch = idx & 7;
            int grow = m0 + r;
            const __half* src = A + (size_t)(grow < Mdim ? grow : 0) * CH + k0 + ch * 8;
            uint32_t byte = (r << 7) + (ch << 4);
            cp_async16(bufb + SWZ(byte), src, grow < Mdim ? 16 : 0);
        }
        #pragma unroll
        for (int i = 0; i < 4; i++) {
            int idx = tid + (i << 8);
            int r = idx >> 3, ch = idx & 7;
            const __half* src = BT + (size_t)(n0 + r) * CH + k0 + ch * 8;
            uint32_t byte = (r << 7) + (ch << 4);
            cp_async16(bufb + 16384 + SWZ(byte), src, 16);
        }
        cp_commit();
    };

    stage(0);
    stage(1);

    const int aRow = wm + (lane & 15);
    const int aKb  = (lane >> 4) << 4;
    const int bRow = wn + (lane & 7) + ((lane & 16) >> 1);
    const int bKb  = (lane & 8) << 1;

    for (int kt = 0; kt < nk; kt++) {
        cp_wait1();
        __syncthreads();
        const uint32_t Ab = sb + (kt % 3) * HSTG;
        const uint32_t Bb = Ab + 16384;
        #pragma unroll
        for (int ks = 0; ks < 4; ks++) {
            uint32_t a[4][4], b[2][4];
            #pragma unroll
            for (int i = 0; i < 4; i++) {
                uint32_t byte = ((aRow + i * 16) << 7) + ks * 32 + aKb;
                ldsm_x4(a[i], Ab + SWZ(byte));
            }
            #pragma unroll
            for (int jj = 0; jj < 2; jj++) {
                uint32_t byte = ((bRow + jj * 16) << 7) + ks * 32 + bKb;
                ldsm_x4(b[jj], Bb + SWZ(byte));
            }
            #pragma unroll
            for (int i = 0; i < 4; i++) {
                mma16816(c[i][0], a[i], b[0][0], b[0][1]);
                mma16816(c[i][1], a[i], b[0][2], b[0][3]);
                mma16816(c[i][2], a[i], b[1][0], b[1][1]);
                mma16816(c[i][3], a[i], b[1][2], b[1][3]);
            }
        }
        __syncthreads();
        if (kt + 2 < nk) stage(kt + 2);
        else cp_commit();
    }

    // epilogue
    if (!split) {
        #pragma unroll
        for (int i = 0; i < 4; i++) {
            int r0 = m0 + wm + i * 16 + g;
            #pragma unroll
            for (int j = 0; j < 4; j++) {
                int col = n0 + wn + j * 8 + 2 * q;
                float b0 = bias[col], b1 = bias[col + 1];
                if (r0 < Mdim) {
                    float* d = od + (size_t)r0 * CH + col;
                    d[0] = c[i][j][0] + b0;
                    d[1] = c[i][j][1] + b1;
                }
                if (r0 + 8 < Mdim) {
                    float* d = od + (size_t)(r0 + 8) * CH + col;
                    d[0] = c[i][j][2] + b0;
                    d[1] = c[i][j][3] + b1;
                }
            }
        }
    } else {
        int sel = n0 / CH;
        int cs  = sel * CH;
        if (sel < 2) {
            float* outp = sel ? ok : oq;
            #pragma unroll
            for (int i = 0; i < 4; i++) {
                int r0 = m0 + wm + i * 16 + g;
                #pragma unroll
                for (int j = 0; j < 4; j++) {
                    int col = n0 + wn + j * 8 + 2 * q;
                    float b0 = bias[col], b1 = bias[col + 1];
                    if (r0 < Mdim) {
                        float* d = outp + (size_t)r0 * CH + (col - cs);
                        d[0] = c[i][j][0] + b0;
                        d[1] = c[i][j][1] + b1;
                    }
                    if (r0 + 8 < Mdim) {
                        float* d = outp + (size_t)(r0 + 8) * CH + (col - cs);
                        d[0] = c[i][j][2] + b0;
                        d[1] = c[i][j][3] + b1;
                    }
                }
            }
        } else {
            #pragma unroll
            for (int i = 0; i < 4; i++) {
                int r0 = m0 + wm + i * 16 + g;
                #pragma unroll
                for (int j = 0; j < 4; j++) {
                    int col = n0 + wn + j * 8 + 2 * q;
                    float b0 = bias[col], b1 = bias[col + 1];
                    if (r0 < Mdim) {
                        __half2* d = (__half2*)(ov + (size_t)r0 * CH + (col - cs));
                        *d = __floats2half2_rn(c[i][j][0] + b0, c[i][j][1] + b1);
                    }
                    if (r0 + 8 < Mdim) {
                        __half2* d = (__half2*)(ov + (size_t)(r0 + 8) * CH + (col - cs));
                        *d = __floats2half2_rn(c[i][j][2] + b0, c[i][j][3] + b1);
                    }
                }
            }
        }
    }
}

// ---------------- RMSNorm over full C per row (fp32 in -> fp16 out, scale folded) ----------------
__global__ void rmsnorm_kernel(const float* __restrict__ qin, const float* __restrict__ kin,
                               __half* __restrict__ qout, __half* __restrict__ kout,
                               const float* __restrict__ qw, const float* __restrict__ kw)
{
    const float* in = blockIdx.y ? kin : qin;
    __half* outp    = blockIdx.y ? kout : qout;
    const float* w  = blockIdx.y ? kw : qw;
    const float post = blockIdx.y ? 1.f : 0.08838834764831845f;   // q: fold attn scale
    const size_t row = blockIdx.x;
    const float4* p  = (const float4*)(in + row * CH);
    const float4* wp = (const float4*)w;

    const int tid = threadIdx.x;
    float ss = 0.f;
    for (int i = tid; i < CH / 4; i += 256) {
        float4 v = p[i];
        ss += v.x * v.x + v.y * v.y + v.z * v.z + v.w * v.w;
    }
    __shared__ float red[8];
    #pragma unroll
    for (int off = 16; off > 0; off >>= 1) ss += __shfl_xor_sync(0xffffffffu, ss, off);
    if ((tid & 31) == 0) red[tid >> 5] = ss;
    __syncthreads();
    float tot = 0.f;
    #pragma unroll
    for (int i = 0; i < 8; i++) tot += red[i];
    const float rms = rsqrtf(tot * (1.f / CH) + EPS) * post;

    __half2* op = (__half2*)(outp + row * CH);
    for (int i = tid; i < CH / 4; i += 256) {
        float4 v = p[i];
        float4 wv = wp[i];
        op[2 * i]     = __floats2half2_rn(v.x * rms * wv.x, v.y * rms * wv.y);
        op[2 * i + 1] = __floats2half2_rn(v.z * rms * wv.z, v.w * rms * wv.w);
    }
}

// ---------------- flash attention, fp16 mma, register-resident P ----------------
// Grid (B*H, 9). Block 256 (8 warps), warp owns 16 q rows. KV tile 64, double-buffered.
// smem rows: 136 halves (272B): 128 data + [V only] col128 = ones (row-sum via mma).
#define ROWB 272
#define AQ_BYTES (128*ROWB)              // 34816
#define KV_BYTES (2*64*ROWB)             // K+V per buffer = 34816
#define ATTN_SMEM (AQ_BYTES + 2*KV_BYTES)  // 104448

__global__ void __launch_bounds__(256, 2) attn_kernel(
    const __half* __restrict__ Q, const __half* __restrict__ K,
    const __half* __restrict__ V, __half* __restrict__ O)
{
    extern __shared__ char smg[];
    const uint32_t sb = smem_u32(smg);
    const int tid  = threadIdx.x;
    const int lane = tid & 31;
    const int wid  = tid >> 5;
    const int g    = lane >> 2;
    const int q    = lane & 3;
    const int bh   = blockIdx.x;
    const int b    = bh / NH;
    const int h    = bh % NH;
    const int q0   = blockIdx.y * 128;
    const size_t rowBase = (size_t)b * SEQ;
    const int nkt = (SEQ + 63) / 64;     // 17

    // issue Q tile loads (group 0)
    for (int i = tid; i < 2048; i += 256) {
        int r = i >> 4, c = i & 15;
        int grow = q0 + r;
        const __half* src = Q + (rowBase + grow) * (size_t)CH + h * HD + c * 8;
        cp_async16(sb + r * ROWB + c * 16, src, grow < SEQ ? 16 : 0);
    }
    cp_commit();

    auto kvstage = [&](int kt) {
        const int k0 = kt * 64;
        const uint32_t bufb = sb + AQ_BYTES + (kt & 1) * KV_BYTES;
        for (int i = tid; i < 1024; i += 256) {
            int r = i >> 4, c = i & 15;
            int krow = k0 + r;
            size_t off = (rowBase + krow) * (size_t)CH + h * HD + c * 8;
            int ok = krow < SEQ ? 16 : 0;
            cp_async16(bufb + r * ROWB + c * 16, K + off, ok);
            cp_async16(bufb + 64 * ROWB + r * ROWB + c * 16, V + off, ok);
        }
        cp_commit();
    };

    kvstage(0);

    // init ones-column (col 128 of V rows) in both buffers; cp.async never touches bytes 256..271
    if (tid < 128) {
        int buf = tid >> 6, r = tid & 63;
        uint4* p = (uint4*)(smg + AQ_BYTES + buf * KV_BYTES + 64 * ROWB + r * ROWB + 256);
        *p = make_uint4(0x00003c00u, 0u, 0u, 0u);   // halves {1,0,0,0,0,0,0,0}
    }

    float o[17][4];
    #pragma unroll
    for (int j = 0; j < 17; j++)
        #pragma unroll
        for (int t = 0; t < 4; t++) o[j][t] = 0.f;
    float mstat0 = -1e30f, mstat1 = -1e30f;

    // precomputed address components
    const uint32_t aQbase = sb + (wid * 16 + (lane & 15)) * ROWB + ((lane >> 4) << 4);
    const int bRowOff = (lane & 7) + ((lane & 16) >> 1);
    const int bKb     = (lane & 8) << 1;
    const int vRowOff = ((lane >> 3) & 1) * 8 + (lane & 7);
    const int vColOff = (lane >> 4) << 4;

    for (int kt = 0; kt < nkt; kt++) {
        if (kt + 1 < nkt) kvstage(kt + 1);
        else cp_commit();
        cp_wait1();                       // Q + KV(kt) resident
        __syncthreads();

        const uint32_t Kb = sb + AQ_BYTES + (kt & 1) * KV_BYTES;
        const uint32_t Vb = Kb + 64 * ROWB;

        // ---- S = Q @ K^T (16 x 64 per warp) ----
        float s[8][4];
        #pragma unroll
        for (int nt = 0; nt < 8; nt++)
            #pragma unroll
            for (int t = 0; t < 4; t++) s[nt][t] = 0.f;
        #pragma unroll
        for (int kb = 0; kb < 8; kb++) {
            uint32_t a[4];
            ldsm_x4(a, aQbase + kb * 32);
            #pragma unroll
            for (int nt = 0; nt < 4; nt++) {
                uint32_t bf[4];
                ldsm_x4(bf, Kb + (nt * 16 + bRowOff) * ROWB + kb * 32 + bKb);
                mma16816(s[2 * nt],     a, bf[0], bf[1]);
                mma16816(s[2 * nt + 1], a, bf[2], bf[3]);
            }
        }

        // ---- mask invalid key columns (last tile) ----
        const int kvalid = SEQ - kt * 64;
        if (kvalid < 64) {
            #pragma unroll
            for (int nt = 0; nt < 8; nt++) {
                int colb = nt * 8 + 2 * q;
                if (colb >= kvalid)     { s[nt][0] = -1e30f; s[nt][2] = -1e30f; }
                if (colb + 1 >= kvalid) { s[nt][1] = -1e30f; s[nt][3] = -1e30f; }
            }
        }

        // ---- online softmax -> P in half2 registers ----
        float cm0 = -1e30f, cm1 = -1e30f;
        #pragma unroll
        for (int nt = 0; nt < 8; nt++) {
            cm0 = fmaxf(cm0, fmaxf(s[nt][0], s[nt][1]));
            cm1 = fmaxf(cm1, fmaxf(s[nt][2], s[nt][3]));
        }
        cm0 = fmaxf(cm0, __shfl_xor_sync(0xffffffffu, cm0, 1));
        cm0 = fmaxf(cm0, __shfl_xor_sync(0xffffffffu, cm0, 2));
        cm1 = fmaxf(cm1, __shfl_xor_sync(0xffffffffu, cm1, 1));
        cm1 = fmaxf(cm1, __shfl_xor_sync(0xffffffffu, cm1, 2));

        const float mn0 = fmaxf(mstat0, cm0);
        const float mn1 = fmaxf(mstat1, cm1);
        const float al0 = __expf(mstat0 - mn0);
        const float al1 = __expf(mstat1 - mn1);
        mstat0 = mn0; mstat1 = mn1;
        const float cc0 = -mn0 * LOG2E;
        const float cc1 = -mn1 * LOG2E;

        uint32_t ph[8][2];
        #pragma unroll
        for (int nt = 0; nt < 8; nt++) {
            ph[nt][0] = ex2_h2(pack_h2(fmaf(s[nt][0], LOG2E, cc0),
                                       fmaf(s[nt][1], LOG2E, cc0)));
            ph[nt][1] = ex2_h2(pack_h2(fmaf(s[nt][2], LOG2E, cc1),
                                       fmaf(s[nt][3], LOG2E, cc1)));
        }

        if (__float_as_uint(al0) != 0x3f800000u || __float_as_uint(al1) != 0x3f800000u) {
            #pragma unroll
            for (int j = 0; j < 17; j++) {
                o[j][0] *= al0; o[j][1] *= al0;
                o[j][2] *= al1; o[j][3] *= al1;
            }
        }

        // ---- O += P @ V  (P register-resident; V via ldmatrix.trans; col128 of V = ones => l) ----
        #pragma unroll
        for (int m = 0; m < 4; m++) {
            uint32_t a[4] = { ph[2 * m][0], ph[2 * m][1], ph[2 * m + 1][0], ph[2 * m + 1][1] };
            const uint32_t vb = Vb + (m * 16 + vRowOff) * ROWB;
            #pragma unroll
            for (int nb = 0; nb < 8; nb++) {
                uint32_t r[4];
                ldsm_x4t(r, vb + nb * 32 + vColOff);
                mma16816(o[2 * nb],     a, r[0], r[1]);
                mma16816(o[2 * nb + 1], a, r[2], r[3]);
            }
            uint32_t rl[2];
            ldsm_x2t(rl, Vb + (m * 16 + vRowOff) * ROWB + 256);
            mma16816(o[16], a, rl[0], rl[1]);
        }
        __syncthreads();   // all warps done reading buffer kt before it is refilled
    }

    // ---- normalize and write ----
    const float l0 = __shfl_sync(0xffffffffu, o[16][0], lane & ~3);
    const float l1 = __shfl_sync(0xffffffffu, o[16][2], lane & ~3);
    const float inv0 = 1.f / l0;
    const float inv1 = 1.f / l1;
    const int row0 = q0 + wid * 16 + g;
    #pragma unroll
    for (int j = 0; j < 16; j++) {
        int col = h * HD + j * 8 + 2 * q;
        if (row0 < SEQ) {
            __half2* d = (__half2*)(O + (rowBase + row0) * (size_t)CH + col);
            *d = __floats2half2_rn(o[j][0] * inv0, o[j][1] * inv0);
        }
        if (row0 + 8 < SEQ) {
            __half2* d = (__half2*)(O + (rowBase + row0 + 8) * (size_t)CH + col);
            *d = __floats2half2_rn(o[j][2] * inv1, o[j][3] * inv1);
        }
    }
}

// ---------------- launch ----------------
extern "C" void kernel_launch(void* const* d_in, const int* in_sizes, int n_in,
                              void* d_out, int out_size)
{
    const float* x     = (const float*)d_in[0];
    const float* qkvW  = (const float*)d_in[1];
    const float* qkvB  = (const float*)d_in[2];
    const float* qNW   = (const float*)d_in[3];
    const float* kNW   = (const float*)d_in[4];
    const float* projW = (const float*)d_in[5];
    const float* projB = (const float*)d_in[6];
    float* out = (float*)d_out;

    __half *pxh, *pwqT, *pwpT, *pqh, *pkh, *pvh, *po;
    float *pq, *pk;
    cudaGetSymbolAddress((void**)&pxh,  g_xh);
    cudaGetSymbolAddress((void**)&pwqT, g_wqkvT);
    cudaGetSymbolAddress((void**)&pwpT, g_wprojT);
    cudaGetSymbolAddress((void**)&pq,   g_q);
    cudaGetSymbolAddress((void**)&pk,   g_k);
    cudaGetSymbolAddress((void**)&pqh,  g_qh);
    cudaGetSymbolAddress((void**)&pkh,  g_kh);
    cudaGetSymbolAddress((void**)&pvh,  g_vh);
    cudaGetSymbolAddress((void**)&po,   g_o);

    cudaFuncSetAttribute(hgemm,       cudaFuncAttributeMaxDynamicSharedMemorySize, HG_SMEM);
    cudaFuncSetAttribute(attn_kernel, cudaFuncAttributeMaxDynamicSharedMemorySize, ATTN_SMEM);

    const int n1 = MROWS * CH;
    f2h_kernel<<<(n1 + 255) / 256, 256>>>(x, pxh, n1);
    transpose_h<<<dim3(3 * CH / 32, CH / 32), dim3(32, 8)>>>(qkvW, pwqT, CH, 3 * CH);
    transpose_h<<<dim3(CH / 32, CH / 32), dim3(32, 8)>>>(projW, pwpT, CH, CH);

    // qkv = x @ W_qkv + b  ->  q(f32), k(f32), v(f16)
    hgemm<<<dim3(65, 75), 256, HG_SMEM>>>(pxh, pwqT, qkvB, pq, pk, pvh, nullptr, MROWS, 1);
    // RMSNorm (q gets attn scale folded) -> fp16
    rmsnorm_kernel<<<dim3(MROWS, 2), 256>>>(pq, pk, pqh, pkh, qNW, kNW);
    // flash attention (fp16 tensor cores) -> fp16
    attn_kernel<<<dim3(BATCH * NH, (SEQ + 127) / 128), 256, ATTN_SMEM>>>(pqh, pkh, pvh, po);
    // out = attn_out @ W_proj + b (fp32 out)
    hgemm<<<dim3(65, 25), 256, HG_SMEM>>>(po, pwpT, projB, nullptr, nullptr, nullptr, out, MROWS, 0);
}

// round 5
// speedup vs baseline: 3.2833x; 1.0320x over previous
#include <cuda_runtime.h>
#include <cuda_fp16.h>
#include <cstdint>
#include <cstddef>

// ---------------- problem constants ----------------
#define BATCH 8
#define SEQ   1025
#define CH    3200
#define NH    25
#define HD    128
#define MROWS (BATCH*SEQ)   // 8200
#define EPS   1e-6f
#define LOG2E 1.4426950408889634f

// ---------------- device scratch (no allocation allowed) ----------------
__device__ __half g_xh  [MROWS*CH];      // fp16 x
__device__ __half g_wqkvT[3*CH*CH];      // fp16, TRANSPOSED qkv weights [3C, C]
__device__ __half g_wprojT[CH*CH];       // fp16, TRANSPOSED proj weights [C, C]
__device__ float  g_q   [MROWS*CH];      // fp32 q (pre-norm)
__device__ float  g_k   [MROWS*CH];      // fp32 k (pre-norm)
__device__ __half g_qh  [MROWS*CH];      // fp16 normalized+scaled q
__device__ __half g_kh  [MROWS*CH];      // fp16 normalized k
__device__ __half g_vh  [MROWS*CH];      // fp16 v
__device__ __half g_o   [MROWS*CH];      // attention output (fp16 for proj GEMM)

// ---------------- PTX helpers ----------------
__device__ __forceinline__ uint32_t smem_u32(const void* p) {
    uint32_t a;
    asm("{ .reg .u64 t; cvta.to.shared.u64 t, %1; cvt.u32.u64 %0, t; }" : "=r"(a) : "l"(p));
    return a;
}

__device__ __forceinline__ void cp_async16(uint32_t smem_addr, const void* gptr, int srcBytes) {
    asm volatile("cp.async.cg.shared.global [%0], [%1], 16, %2;\n"
                 :: "r"(smem_addr), "l"(gptr), "r"(srcBytes) : "memory");
}
__device__ __forceinline__ void cp_async16u(uint32_t smem_addr, const void* gptr) {
    asm volatile("cp.async.cg.shared.global [%0], [%1], 16;\n"
                 :: "r"(smem_addr), "l"(gptr) : "memory");
}
__device__ __forceinline__ void cp_commit() {
    asm volatile("cp.async.commit_group;\n" ::: "memory");
}
__device__ __forceinline__ void cp_wait1() {
    asm volatile("cp.async.wait_group 1;\n" ::: "memory");
}

__device__ __forceinline__ void ldsm_x4(uint32_t r[4], uint32_t addr) {
    asm volatile("ldmatrix.sync.aligned.m8n8.x4.shared.b16 {%0,%1,%2,%3}, [%4];"
                 : "=r"(r[0]), "=r"(r[1]), "=r"(r[2]), "=r"(r[3]) : "r"(addr));
}
__device__ __forceinline__ void ldsm_x4t(uint32_t r[4], uint32_t addr) {
    asm volatile("ldmatrix.sync.aligned.m8n8.x4.trans.shared.b16 {%0,%1,%2,%3}, [%4];"
                 : "=r"(r[0]), "=r"(r[1]), "=r"(r[2]), "=r"(r[3]) : "r"(addr));
}
__device__ __forceinline__ void ldsm_x2t(uint32_t r[2], uint32_t addr) {
    asm volatile("ldmatrix.sync.aligned.m8n8.x2.trans.shared.b16 {%0,%1}, [%2];"
                 : "=r"(r[0]), "=r"(r[1]) : "r"(addr));
}

__device__ __forceinline__ void mma16816(float c[4], const uint32_t a[4],
                                         uint32_t b0, uint32_t b1) {
    asm volatile(
        "mma.sync.aligned.m16n8k16.row.col.f32.f16.f16.f32 "
        "{%0,%1,%2,%3}, {%4,%5,%6,%7}, {%8,%9}, {%0,%1,%2,%3};\n"
        : "+f"(c[0]), "+f"(c[1]), "+f"(c[2]), "+f"(c[3])
        : "r"(a[0]), "r"(a[1]), "r"(a[2]), "r"(a[3]), "r"(b0), "r"(b1));
}

__device__ __forceinline__ uint32_t ex2_h2(uint32_t x) {
    uint32_t r;
    asm volatile("ex2.approx.f16x2 %0, %1;" : "=r"(r) : "r"(x));
    return r;
}

__device__ __forceinline__ uint32_t pack_h2(float lo, float hi) {
    __half2 h = __floats2half2_rn(lo, hi);
    return *reinterpret_cast<uint32_t*>(&h);
}

#define SWZ(b) ((b) ^ (((b) >> 3) & 0x70))

// ---------------- prep kernels ----------------
__global__ void f2h_kernel(const float4* __restrict__ in, uint2* __restrict__ out, int n4) {
    int i = blockIdx.x * blockDim.x + threadIdx.x;
    if (i < n4) {
        float4 v = in[i];
        __half2 lo = __floats2half2_rn(v.x, v.y);
        __half2 hi = __floats2half2_rn(v.z, v.w);
        uint2 u;
        u.x = *reinterpret_cast<uint32_t*>(&lo);
        u.y = *reinterpret_cast<uint32_t*>(&hi);
        out[i] = u;
    }
}

// out[n][k] = half(in[k][n])
__global__ void transpose_h(const float* __restrict__ in, __half* __restrict__ out,
                            int K, int N) {
    __shared__ float t[32][33];
    const int nb = blockIdx.x * 32, kb = blockIdx.y * 32;
    const int tx = threadIdx.x, ty = threadIdx.y;
    #pragma unroll
    for (int j = 0; j < 32; j += 8)
        t[ty + j][tx] = in[(size_t)(kb + ty + j) * N + nb + tx];
    __syncthreads();
    #pragma unroll
    for (int j = 0; j < 32; j += 8)
        out[(size_t)(nb + ty + j) * K + kb + tx] = __float2half_rn(t[tx][ty + j]);
}

// ---------------- fp16 GEMM (ldmatrix + m16n8k16): C[M,*] = A @ BT^T + bias ----------------
#define HSTG 32768
#define HG_SMEM (3*HSTG)

__global__ void __launch_bounds__(256, 2) hgemm(
    const __half* __restrict__ A, const __half* __restrict__ BT,
    const float* __restrict__ bias,
    float* __restrict__ oq, float* __restrict__ ok, __half* __restrict__ ov,
    float* __restrict__ od,
    int Mdim, int split)
{
    extern __shared__ char smg[];
    const uint32_t sb = smem_u32(smg);
    const int tid  = threadIdx.x;
    const int lane = tid & 31;
    const int wid  = tid >> 5;
    const int g    = lane >> 2;
    const int q    = lane & 3;
    const int m0   = blockIdx.x * 128;
    const int n0   = blockIdx.y * 128;
    const int wm   = (wid >> 2) * 64;
    const int wn   = (wid & 3) * 32;
    const int nk   = CH / 64;
    const bool fullM = (m0 + 128 <= Mdim);

    float c[4][4][4];
    #pragma unroll
    for (int i = 0; i < 4; i++)
        #pragma unroll
        for (int j = 0; j < 4; j++)
            #pragma unroll
            for (int t = 0; t < 4; t++) c[i][j][t] = 0.f;

    // per-thread load roles (precomputed)
    const int ldR = tid >> 3, ldC = tid & 7;

    auto stage = [&](int ts) {
        const int k0 = ts * 64;
        const uint32_t bufb = sb + (ts % 3) * HSTG;
        if (fullM) {
            #pragma unroll
            for (int i = 0; i < 4; i++) {
                int r = ldR + (i << 5);
                const __half* src = A + (size_t)(m0 + r) * CH + k0 + ldC * 8;
                uint32_t byte = (r << 7) + (ldC << 4);
                cp_async16u(bufb + SWZ(byte), src);
            }
        } else {
            #pragma unroll
            for (int i = 0; i < 4; i++) {
                int r = ldR + (i << 5);
                int grow = m0 + r;
                const __half* src = A + (size_t)(grow < Mdim ? grow : 0) * CH + k0 + ldC * 8;
                uint32_t byte = (r << 7) + (ldC << 4);
                cp_async16(bufb + SWZ(byte), src, grow < Mdim ? 16 : 0);
            }
        }
        #pragma unroll
        for (int i = 0; i < 4; i++) {
            int r = ldR + (i << 5);
            const __half* src = BT + (size_t)(n0 + r) * CH + k0 + ldC * 8;
            uint32_t byte = (r << 7) + (ldC << 4);
            cp_async16u(bufb + 16384 + SWZ(byte), src);
        }
        cp_commit();
    };

    stage(0);
    stage(1);

    const int aRow = wm + (lane & 15);
    const int aKb  = (lane >> 4) << 4;
    const int bRow = wn + (lane & 7) + ((lane & 16) >> 1);
    const int bKb  = (lane & 8) << 1;

    for (int kt = 0; kt < nk; kt++) {
        cp_wait1();
        __syncthreads();
        // Buffer (kt+2)%3 was consumed in iteration kt-1; the barrier above
        // ordered all warps past those reads, so refill it now (overlaps MMAs).
        if (kt + 2 < nk) stage(kt + 2);
        else cp_commit();                 // keep group-count invariant

        const uint32_t Ab = sb + (kt % 3) * HSTG;
        const uint32_t Bb = Ab + 16384;
        #pragma unroll
        for (int ks = 0; ks < 4; ks++) {
            uint32_t a[4][4], b[2][4];
            #pragma unroll
            for (int i = 0; i < 4; i++) {
                uint32_t byte = ((aRow + i * 16) << 7) + ks * 32 + aKb;
                ldsm_x4(a[i], Ab + SWZ(byte));
            }
            #pragma unroll
            for (int jj = 0; jj < 2; jj++) {
                uint32_t byte = ((bRow + jj * 16) << 7) + ks * 32 + bKb;
                ldsm_x4(b[jj], Bb + SWZ(byte));
            }
            #pragma unroll
            for (int i = 0; i < 4; i++) {
                mma16816(c[i][0], a[i], b[0][0], b[0][1]);
                mma16816(c[i][1], a[i], b[0][2], b[0][3]);
                mma16816(c[i][2], a[i], b[1][0], b[1][1]);
                mma16816(c[i][3], a[i], b[1][2], b[1][3]);
            }
        }
    }

    // epilogue
    if (!split) {
        #pragma unroll
        for (int i = 0; i < 4; i++) {
            int r0 = m0 + wm + i * 16 + g;
            #pragma unroll
            for (int j = 0; j < 4; j++) {
                int col = n0 + wn + j * 8 + 2 * q;
                float b0 = bias[col], b1 = bias[col + 1];
                if (r0 < Mdim) {
                    float* d = od + (size_t)r0 * CH + col;
                    d[0] = c[i][j][0] + b0;
                    d[1] = c[i][j][1] + b1;
                }
                if (r0 + 8 < Mdim) {
                    float* d = od + (size_t)(r0 + 8) * CH + col;
                    d[0] = c[i][j][2] + b0;
                    d[1] = c[i][j][3] + b1;
                }
            }
        }
    } else {
        int sel = n0 / CH;
        int cs  = sel * CH;
        if (sel < 2) {
            float* outp = sel ? ok : oq;
            #pragma unroll
            for (int i = 0; i < 4; i++) {
                int r0 = m0 + wm + i * 16 + g;
                #pragma unroll
                for (int j = 0; j < 4; j++) {
                    int col = n0 + wn + j * 8 + 2 * q;
                    float b0 = bias[col], b1 = bias[col + 1];
                    if (r0 < Mdim) {
                        float* d = outp + (size_t)r0 * CH + (col - cs);
                        d[0] = c[i][j][0] + b0;
                        d[1] = c[i][j][1] + b1;
                    }
                    if (r0 + 8 < Mdim) {
                        float* d = outp + (size_t)(r0 + 8) * CH + (col - cs);
                        d[0] = c[i][j][2] + b0;
                        d[1] = c[i][j][3] + b1;
                    }
                }
            }
        } else {
            #pragma unroll
            for (int i = 0; i < 4; i++) {
                int r0 = m0 + wm + i * 16 + g;
                #pragma unroll
                for (int j = 0; j < 4; j++) {
                    int col = n0 + wn + j * 8 + 2 * q;
                    float b0 = bias[col], b1 = bias[col + 1];
                    if (r0 < Mdim) {
                        __half2* d = (__half2*)(ov + (size_t)r0 * CH + (col - cs));
                        *d = __floats2half2_rn(c[i][j][0] + b0, c[i][j][1] + b1);
                    }
                    if (r0 + 8 < Mdim) {
                        __half2* d = (__half2*)(ov + (size_t)(r0 + 8) * CH + (col - cs));
                        *d = __floats2half2_rn(c[i][j][2] + b0, c[i][j][3] + b1);
                    }
                }
            }
        }
    }
}

// ---------------- RMSNorm over full C per row (fp32 in -> fp16 out, scale folded) ----------------
__global__ void rmsnorm_kernel(const float* __restrict__ qin, const float* __restrict__ kin,
                               __half* __restrict__ qout, __half* __restrict__ kout,
                               const float* __restrict__ qw, const float* __restrict__ kw)
{
    const float* in = blockIdx.y ? kin : qin;
    __half* outp    = blockIdx.y ? kout : qout;
    const float* w  = blockIdx.y ? kw : qw;
    const float post = blockIdx.y ? 1.f : 0.08838834764831845f;   // q: fold attn scale
    const size_t row = blockIdx.x;
    const float4* p  = (const float4*)(in + row * CH);
    const float4* wp = (const float4*)w;

    const int tid = threadIdx.x;
    float ss = 0.f;
    for (int i = tid; i < CH / 4; i += 256) {
        float4 v = p[i];
        ss += v.x * v.x + v.y * v.y + v.z * v.z + v.w * v.w;
    }
    __shared__ float red[8];
    #pragma unroll
    for (int off = 16; off > 0; off >>= 1) ss += __shfl_xor_sync(0xffffffffu, ss, off);
    if ((tid & 31) == 0) red[tid >> 5] = ss;
    __syncthreads();
    float tot = 0.f;
    #pragma unroll
    for (int i = 0; i < 8; i++) tot += red[i];
    const float rms = rsqrtf(tot * (1.f / CH) + EPS) * post;

    __half2* op = (__half2*)(outp + row * CH);
    for (int i = tid; i < CH / 4; i += 256) {
        float4 v = p[i];
        float4 wv = wp[i];
        op[2 * i]     = __floats2half2_rn(v.x * rms * wv.x, v.y * rms * wv.y);
        op[2 * i + 1] = __floats2half2_rn(v.z * rms * wv.z, v.w * rms * wv.w);
    }
}

// ---------------- flash attention, fp16 mma, register-resident P ----------------
#define ROWB 272
#define AQ_BYTES (128*ROWB)
#define KV_BYTES (2*64*ROWB)
#define ATTN_SMEM (AQ_BYTES + 2*KV_BYTES)  // 104448

__global__ void __launch_bounds__(256, 2) attn_kernel(
    const __half* __restrict__ Q, const __half* __restrict__ K,
    const __half* __restrict__ V, __half* __restrict__ O)
{
    extern __shared__ char smg[];
    const uint32_t sb = smem_u32(smg);
    const int tid  = threadIdx.x;
    const int lane = tid & 31;
    const int wid  = tid >> 5;
    const int g    = lane >> 2;
    const int q    = lane & 3;
    const int bh   = blockIdx.x;
    const int b    = bh / NH;
    const int h    = bh % NH;
    const int q0   = blockIdx.y * 128;
    const size_t rowBase = (size_t)b * SEQ;
    const int nkt = (SEQ + 63) / 64;     // 17

    for (int i = tid; i < 2048; i += 256) {
        int r = i >> 4, c = i & 15;
        int grow = q0 + r;
        const __half* src = Q + (rowBase + grow) * (size_t)CH + h * HD + c * 8;
        cp_async16(sb + r * ROWB + c * 16, src, grow < SEQ ? 16 : 0);
    }
    cp_commit();

    auto kvstage = [&](int kt) {
        const int k0 = kt * 64;
        const uint32_t bufb = sb + AQ_BYTES + (kt & 1) * KV_BYTES;
        for (int i = tid; i < 1024; i += 256) {
            int r = i >> 4, c = i & 15;
            int krow = k0 + r;
            size_t off = (rowBase + krow) * (size_t)CH + h * HD + c * 8;
            int ok = krow < SEQ ? 16 : 0;
            cp_async16(bufb + r * ROWB + c * 16, K + off, ok);
            cp_async16(bufb + 64 * ROWB + r * ROWB + c * 16, V + off, ok);
        }
        cp_commit();
    };

    kvstage(0);

    if (tid < 128) {
        int buf = tid >> 6, r = tid & 63;
        uint4* p = (uint4*)(smg + AQ_BYTES + buf * KV_BYTES + 64 * ROWB + r * ROWB + 256);
        *p = make_uint4(0x00003c00u, 0u, 0u, 0u);   // halves {1,0,0,0,0,0,0,0}
    }

    float o[17][4];
    #pragma unroll
    for (int j = 0; j < 17; j++)
        #pragma unroll
        for (int t = 0; t < 4; t++) o[j][t] = 0.f;
    float mstat0 = -1e30f, mstat1 = -1e30f;

    const uint32_t aQbase = sb + (wid * 16 + (lane & 15)) * ROWB + ((lane >> 4) << 4);
    const int bRowOff = (lane & 7) + ((lane & 16) >> 1);
    const int bKb     = (lane & 8) << 1;
    const int vRowOff = ((lane >> 3) & 1) * 8 + (lane & 7);
    const int vColOff = (lane >> 4) << 4;

    for (int kt = 0; kt < nkt; kt++) {
        if (kt + 1 < nkt) kvstage(kt + 1);
        else cp_commit();
        cp_wait1();
        __syncthreads();

        const uint32_t Kb = sb + AQ_BYTES + (kt & 1) * KV_BYTES;
        const uint32_t Vb = Kb + 64 * ROWB;

        float s[8][4];
        #pragma unroll
        for (int nt = 0; nt < 8; nt++)
            #pragma unroll
            for (int t = 0; t < 4; t++) s[nt][t] = 0.f;
        #pragma unroll
        for (int kb = 0; kb < 8; kb++) {
            uint32_t a[4];
            ldsm_x4(a, aQbase + kb * 32);
            #pragma unroll
            for (int nt = 0; nt < 4; nt++) {
                uint32_t bf[4];
                ldsm_x4(bf, Kb + (nt * 16 + bRowOff) * ROWB + kb * 32 + bKb);
                mma16816(s[2 * nt],     a, bf[0], bf[1]);
                mma16816(s[2 * nt + 1], a, bf[2], bf[3]);
            }
        }

        const int kvalid = SEQ - kt * 64;
        if (kvalid < 64) {
            #pragma unroll
            for (int nt = 0; nt < 8; nt++) {
                int colb = nt * 8 + 2 * q;
                if (colb >= kvalid)     { s[nt][0] = -1e30f; s[nt][2] = -1e30f; }
                if (colb + 1 >= kvalid) { s[nt][1] = -1e30f; s[nt][3] = -1e30f; }
            }
        }

        float cm0 = -1e30f, cm1 = -1e30f;
        #pragma unroll
        for (int nt = 0; nt < 8; nt++) {
            cm0 = fmaxf(cm0, fmaxf(s[nt][0], s[nt][1]));
            cm1 = fmaxf(cm1, fmaxf(s[nt][2], s[nt][3]));
        }
        cm0 = fmaxf(cm0, __shfl_xor_sync(0xffffffffu, cm0, 1));
        cm0 = fmaxf(cm0, __shfl_xor_sync(0xffffffffu, cm0, 2));
        cm1 = fmaxf(cm1, __shfl_xor_sync(0xffffffffu, cm1, 1));
        cm1 = fmaxf(cm1, __shfl_xor_sync(0xffffffffu, cm1, 2));

        const float mn0 = fmaxf(mstat0, cm0);
        const float mn1 = fmaxf(mstat1, cm1);
        const float al0 = __expf(mstat0 - mn0);
        const float al1 = __expf(mstat1 - mn1);
        mstat0 = mn0; mstat1 = mn1;
        const float cc0 = -mn0 * LOG2E;
        const float cc1 = -mn1 * LOG2E;

        uint32_t ph[8][2];
        #pragma unroll
        for (int nt = 0; nt < 8; nt++) {
            ph[nt][0] = ex2_h2(pack_h2(fmaf(s[nt][0], LOG2E, cc0),
                                       fmaf(s[nt][1], LOG2E, cc0)));
            ph[nt][1] = ex2_h2(pack_h2(fmaf(s[nt][2], LOG2E, cc1),
                                       fmaf(s[nt][3], LOG2E, cc1)));
        }

        if (__float_as_uint(al0) != 0x3f800000u || __float_as_uint(al1) != 0x3f800000u) {
            #pragma unroll
            for (int j = 0; j < 17; j++) {
                o[j][0] *= al0; o[j][1] *= al0;
                o[j][2] *= al1; o[j][3] *= al1;
            }
        }

        #pragma unroll
        for (int m = 0; m < 4; m++) {
            uint32_t a[4] = { ph[2 * m][0], ph[2 * m][1], ph[2 * m + 1][0], ph[2 * m + 1][1] };
            const uint32_t vb = Vb + (m * 16 + vRowOff) * ROWB;
            #pragma unroll
            for (int nb = 0; nb < 8; nb++) {
                uint32_t r[4];
                ldsm_x4t(r, vb + nb * 32 + vColOff);
                mma16816(o[2 * nb],     a, r[0], r[1]);
                mma16816(o[2 * nb + 1], a, r[2], r[3]);
            }
            uint32_t rl[2];
            ldsm_x2t(rl, Vb + (m * 16 + vRowOff) * ROWB + 256);
            mma16816(o[16], a, rl[0], rl[1]);
        }
        __syncthreads();
    }

    const float l0 = __shfl_sync(0xffffffffu, o[16][0], lane & ~3);
    const float l1 = __shfl_sync(0xffffffffu, o[16][2], lane & ~3);
    const float inv0 = 1.f / l0;
    const float inv1 = 1.f / l1;
    const int row0 = q0 + wid * 16 + g;
    #pragma unroll
    for (int j = 0; j < 16; j++) {
        int col = h * HD + j * 8 + 2 * q;
        if (row0 < SEQ) {
            __half2* d = (__half2*)(O + (rowBase + row0) * (size_t)CH + col);
            *d = __floats2half2_rn(o[j][0] * inv0, o[j][1] * inv0);
        }
        if (row0 + 8 < SEQ) {
            __half2* d = (__half2*)(O + (rowBase + row0 + 8) * (size_t)CH + col);
            *d = __floats2half2_rn(o[j][2] * inv1, o[j][3] * inv1);
        }
    }
}

// ---------------- launch ----------------
extern "C" void kernel_launch(void* const* d_in, const int* in_sizes, int n_in,
                              void* d_out, int out_size)
{
    const float* x     = (const float*)d_in[0];
    const float* qkvW  = (const float*)d_in[1];
    const float* qkvB  = (const float*)d_in[2];
    const float* qNW   = (const float*)d_in[3];
    const float* kNW   = (const float*)d_in[4];
    const float* projW = (const float*)d_in[5];
    const float* projB = (const float*)d_in[6];
    float* out = (float*)d_out;

    __half *pxh, *pwqT, *pwpT, *pqh, *pkh, *pvh, *po;
    float *pq, *pk;
    cudaGetSymbolAddress((void**)&pxh,  g_xh);
    cudaGetSymbolAddress((void**)&pwqT, g_wqkvT);
    cudaGetSymbolAddress((void**)&pwpT, g_wprojT);
    cudaGetSymbolAddress((void**)&pq,   g_q);
    cudaGetSymbolAddress((void**)&pk,   g_k);
    cudaGetSymbolAddress((void**)&pqh,  g_qh);
    cudaGetSymbolAddress((void**)&pkh,  g_kh);
    cudaGetSymbolAddress((void**)&pvh,  g_vh);
    cudaGetSymbolAddress((void**)&po,   g_o);

    cudaFuncSetAttribute(hgemm,       cudaFuncAttributeMaxDynamicSharedMemorySize, HG_SMEM);
    cudaFuncSetAttribute(attn_kernel, cudaFuncAttributeMaxDynamicSharedMemorySize, ATTN_SMEM);

    const int n1 = MROWS * CH;
    f2h_kernel<<<(n1 / 4 + 255) / 256, 256>>>((const float4*)x, (uint2*)pxh, n1 / 4);
    transpose_h<<<dim3(3 * CH / 32, CH / 32), dim3(32, 8)>>>(qkvW, pwqT, CH, 3 * CH);
    transpose_h<<<dim3(CH / 32, CH / 32), dim3(32, 8)>>>(projW, pwpT, CH, CH);

    // qkv = x @ W_qkv + b  ->  q(f32), k(f32), v(f16)
    hgemm<<<dim3(65, 75), 256, HG_SMEM>>>(pxh, pwqT, qkvB, pq, pk, pvh, nullptr, MROWS, 1);
    // RMSNorm (q gets attn scale folded) -> fp16
    rmsnorm_kernel<<<dim3(MROWS, 2), 256>>>(pq, pk, pqh, pkh, qNW, kNW);
    // flash attention (fp16 tensor cores) -> fp16
    attn_kernel<<<dim3(BATCH * NH, (SEQ + 127) / 128), 256, ATTN_SMEM>>>(pqh, pkh, pvh, po);
    // out = attn_out @ W_proj + b (fp32 out)
    hgemm<<<dim3(65, 25), 256, HG_SMEM>>>(po, pwpT, projB, nullptr, nullptr, nullptr, out, MROWS, 0);
}

// round 6
// speedup vs baseline: 3.2853x; 1.0006x over previous
#include <cuda_runtime.h>
#include <cuda_fp16.h>
#include <cstdint>
#include <cstddef>

// ---------------- problem constants ----------------
#define BATCH 8
#define SEQ   1025
#define CH    3200
#define NH    25
#define HD    128
#define MROWS (BATCH*SEQ)   // 8200
#define EPS   1e-6f
#define LOG2E 1.4426950408889634f

// ---------------- device scratch (no allocation allowed) ----------------
__device__ __half g_xh  [MROWS*CH];      // fp16 x
__device__ __half g_wqkvT[3*CH*CH];      // fp16, TRANSPOSED qkv weights [3C, C]
__device__ __half g_wprojT[CH*CH];       // fp16, TRANSPOSED proj weights [C, C]
__device__ float  g_q   [MROWS*CH];      // fp32 q (pre-norm)
__device__ float  g_k   [MROWS*CH];      // fp32 k (pre-norm)
__device__ __half g_qh  [MROWS*CH];      // fp16 normalized+scaled q
__device__ __half g_kh  [MROWS*CH];      // fp16 normalized k
__device__ __half g_vh  [MROWS*CH];      // fp16 v
__device__ __half g_o   [MROWS*CH];      // attention output (fp16 for proj GEMM)

// ---------------- PTX helpers ----------------
__device__ __forceinline__ uint32_t smem_u32(const void* p) {
    uint32_t a;
    asm("{ .reg .u64 t; cvta.to.shared.u64 t, %1; cvt.u32.u64 %0, t; }" : "=r"(a) : "l"(p));
    return a;
}

__device__ __forceinline__ void cp_async16(uint32_t smem_addr, const void* gptr, int srcBytes) {
    asm volatile("cp.async.cg.shared.global [%0], [%1], 16, %2;\n"
                 :: "r"(smem_addr), "l"(gptr), "r"(srcBytes) : "memory");
}
__device__ __forceinline__ void cp_async16u(uint32_t smem_addr, const void* gptr) {
    asm volatile("cp.async.cg.shared.global [%0], [%1], 16;\n"
                 :: "r"(smem_addr), "l"(gptr) : "memory");
}
__device__ __forceinline__ void cp_commit() {
    asm volatile("cp.async.commit_group;\n" ::: "memory");
}
__device__ __forceinline__ void cp_wait1() {
    asm volatile("cp.async.wait_group 1;\n" ::: "memory");
}

__device__ __forceinline__ void ldsm_x4(uint32_t r[4], uint32_t addr) {
    asm volatile("ldmatrix.sync.aligned.m8n8.x4.shared.b16 {%0,%1,%2,%3}, [%4];"
                 : "=r"(r[0]), "=r"(r[1]), "=r"(r[2]), "=r"(r[3]) : "r"(addr));
}
__device__ __forceinline__ void ldsm_x4t(uint32_t r[4], uint32_t addr) {
    asm volatile("ldmatrix.sync.aligned.m8n8.x4.trans.shared.b16 {%0,%1,%2,%3}, [%4];"
                 : "=r"(r[0]), "=r"(r[1]), "=r"(r[2]), "=r"(r[3]) : "r"(addr));
}
__device__ __forceinline__ void ldsm_x2t(uint32_t r[2], uint32_t addr) {
    asm volatile("ldmatrix.sync.aligned.m8n8.x2.trans.shared.b16 {%0,%1}, [%2];"
                 : "=r"(r[0]), "=r"(r[1]) : "r"(addr));
}

__device__ __forceinline__ void mma16816(float c[4], const uint32_t a[4],
                                         uint32_t b0, uint32_t b1) {
    asm volatile(
        "mma.sync.aligned.m16n8k16.row.col.f32.f16.f16.f32 "
        "{%0,%1,%2,%3}, {%4,%5,%6,%7}, {%8,%9}, {%0,%1,%2,%3};\n"
        : "+f"(c[0]), "+f"(c[1]), "+f"(c[2]), "+f"(c[3])
        : "r"(a[0]), "r"(a[1]), "r"(a[2]), "r"(a[3]), "r"(b0), "r"(b1));
}

__device__ __forceinline__ uint32_t ex2_h2(uint32_t x) {
    uint32_t r;
    asm volatile("ex2.approx.f16x2 %0, %1;" : "=r"(r) : "r"(x));
    return r;
}

__device__ __forceinline__ uint32_t pack_h2(float lo, float hi) {
    __half2 h = __floats2half2_rn(lo, hi);
    return *reinterpret_cast<uint32_t*>(&h);
}

#define SWZ(b) ((b) ^ (((b) >> 3) & 0x70))

// ---------------- prep kernels ----------------
__global__ void f2h_kernel(const float4* __restrict__ in, uint2* __restrict__ out, int n4) {
    int i = blockIdx.x * blockDim.x + threadIdx.x;
    if (i < n4) {
        float4 v = in[i];
        __half2 lo = __floats2half2_rn(v.x, v.y);
        __half2 hi = __floats2half2_rn(v.z, v.w);
        uint2 u;
        u.x = *reinterpret_cast<uint32_t*>(&lo);
        u.y = *reinterpret_cast<uint32_t*>(&hi);
        out[i] = u;
    }
}

// out[n][k] = half(in[k][n])
__global__ void transpose_h(const float* __restrict__ in, __half* __restrict__ out,
                            int K, int N) {
    __shared__ float t[32][33];
    const int nb = blockIdx.x * 32, kb = blockIdx.y * 32;
    const int tx = threadIdx.x, ty = threadIdx.y;
    #pragma unroll
    for (int j = 0; j < 32; j += 8)
        t[ty + j][tx] = in[(size_t)(kb + ty + j) * N + nb + tx];
    __syncthreads();
    #pragma unroll
    for (int j = 0; j < 32; j += 8)
        out[(size_t)(nb + ty + j) * K + kb + tx] = __float2half_rn(t[tx][ty + j]);
}

// ---------------- fp16 GEMM: 128x128 CTA tile, 4 warps x (64x64) warp tile ----------------
// smem traffic per ktile: A reads x2 + B reads x2 (96KB) < tensor time -> tensor-bound.
#define HSTG 32768
#define HG_SMEM (3*HSTG)

__global__ void __launch_bounds__(128, 2) hgemm(
    const __half* __restrict__ A, const __half* __restrict__ BT,
    const float* __restrict__ bias,
    float* __restrict__ oq, float* __restrict__ ok, __half* __restrict__ ov,
    float* __restrict__ od,
    int Mdim, int split)
{
    extern __shared__ char smg[];
    const uint32_t sb = smem_u32(smg);
    const int tid  = threadIdx.x;
    const int lane = tid & 31;
    const int wid  = tid >> 5;          // 0..3
    const int g    = lane >> 2;
    const int q    = lane & 3;
    const int m0   = blockIdx.x * 128;
    const int n0   = blockIdx.y * 128;
    const int wm   = (wid & 1) * 64;    // warp M offset
    const int wn   = (wid >> 1) * 64;   // warp N offset
    const int nk   = CH / 64;           // 50
    const bool fullM = (m0 + 128 <= Mdim);

    float c[4][8][4];
    #pragma unroll
    for (int i = 0; i < 4; i++)
        #pragma unroll
        for (int j = 0; j < 8; j++)
            #pragma unroll
            for (int t = 0; t < 4; t++) c[i][j][t] = 0.f;

    const int ldR = tid >> 3, ldC = tid & 7;   // 16 rows x 8 chunks per pass

    auto stage = [&](int ts) {
        const int k0 = ts * 64;
        const uint32_t bufb = sb + (ts % 3) * HSTG;
        if (fullM) {
            #pragma unroll
            for (int i = 0; i < 8; i++) {
                int r = ldR + (i << 4);
                const __half* src = A + (size_t)(m0 + r) * CH + k0 + ldC * 8;
                uint32_t byte = (r << 7) + (ldC << 4);
                cp_async16u(bufb + SWZ(byte), src);
            }
        } else {
            #pragma unroll
            for (int i = 0; i < 8; i++) {
                int r = ldR + (i << 4);
                int grow = m0 + r;
                const __half* src = A + (size_t)(grow < Mdim ? grow : 0) * CH + k0 + ldC * 8;
                uint32_t byte = (r << 7) + (ldC << 4);
                cp_async16(bufb + SWZ(byte), src, grow < Mdim ? 16 : 0);
            }
        }
        #pragma unroll
        for (int i = 0; i < 8; i++) {
            int r = ldR + (i << 4);
            const __half* src = BT + (size_t)(n0 + r) * CH + k0 + ldC * 8;
            uint32_t byte = (r << 7) + (ldC << 4);
            cp_async16u(bufb + 16384 + SWZ(byte), src);
        }
        cp_commit();
    };

    stage(0);
    stage(1);

    const int aRow = wm + (lane & 15);
    const int aKb  = (lane >> 4) << 4;
    const int bRow = wn + (lane & 7) + ((lane & 16) >> 1);
    const int bKb  = (lane & 8) << 1;

    for (int kt = 0; kt < nk; kt++) {
        cp_wait1();
        __syncthreads();
        if (kt + 2 < nk) stage(kt + 2);
        else cp_commit();                 // keep group-count invariant

        const uint32_t Ab = sb + (kt % 3) * HSTG;
        const uint32_t Bb = Ab + 16384;
        #pragma unroll
        for (int ks = 0; ks < 4; ks++) {
            uint32_t a[4][4], b[4][4];
            #pragma unroll
            for (int i = 0; i < 4; i++) {
                uint32_t byte = ((aRow + i * 16) << 7) + ks * 32 + aKb;
                ldsm_x4(a[i], Ab + SWZ(byte));
            }
            #pragma unroll
            for (int j = 0; j < 4; j++) {
                uint32_t byte = ((bRow + j * 16) << 7) + ks * 32 + bKb;
                ldsm_x4(b[j], Bb + SWZ(byte));
            }
            #pragma unroll
            for (int i = 0; i < 4; i++)
                #pragma unroll
                for (int j = 0; j < 4; j++) {
                    mma16816(c[i][2 * j],     a[i], b[j][0], b[j][1]);
                    mma16816(c[i][2 * j + 1], a[i], b[j][2], b[j][3]);
                }
        }
    }

    // epilogue: warp writes rows [wm,wm+64) x cols [wn,wn+64)
    if (!split) {
        #pragma unroll
        for (int i = 0; i < 4; i++) {
            int r0 = m0 + wm + i * 16 + g;
            #pragma unroll
            for (int j = 0; j < 8; j++) {
                int col = n0 + wn + j * 8 + 2 * q;
                float b0 = bias[col], b1 = bias[col + 1];
                if (r0 < Mdim) {
                    float* d = od + (size_t)r0 * CH + col;
                    d[0] = c[i][j][0] + b0;
                    d[1] = c[i][j][1] + b1;
                }
                if (r0 + 8 < Mdim) {
                    float* d = od + (size_t)(r0 + 8) * CH + col;
                    d[0] = c[i][j][2] + b0;
                    d[1] = c[i][j][3] + b1;
                }
            }
        }
    } else {
        int sel = n0 / CH;
        int cs  = sel * CH;
        if (sel < 2) {
            float* outp = sel ? ok : oq;
            #pragma unroll
            for (int i = 0; i < 4; i++) {
                int r0 = m0 + wm + i * 16 + g;
                #pragma unroll
                for (int j = 0; j < 8; j++) {
                    int col = n0 + wn + j * 8 + 2 * q;
                    float b0 = bias[col], b1 = bias[col + 1];
                    if (r0 < Mdim) {
                        float* d = outp + (size_t)r0 * CH + (col - cs);
                        d[0] = c[i][j][0] + b0;
                        d[1] = c[i][j][1] + b1;
                    }
                    if (r0 + 8 < Mdim) {
                        float* d = outp + (size_t)(r0 + 8) * CH + (col - cs);
                        d[0] = c[i][j][2] + b0;
                        d[1] = c[i][j][3] + b1;
                    }
                }
            }
        } else {
            #pragma unroll
            for (int i = 0; i < 4; i++) {
                int r0 = m0 + wm + i * 16 + g;
                #pragma unroll
                for (int j = 0; j < 8; j++) {
                    int col = n0 + wn + j * 8 + 2 * q;
                    float b0 = bias[col], b1 = bias[col + 1];
                    if (r0 < Mdim) {
                        __half2* d = (__half2*)(ov + (size_t)r0 * CH + (col - cs));
                        *d = __floats2half2_rn(c[i][j][0] + b0, c[i][j][1] + b1);
                    }
                    if (r0 + 8 < Mdim) {
                        __half2* d = (__half2*)(ov + (size_t)(r0 + 8) * CH + (col - cs));
                        *d = __floats2half2_rn(c[i][j][2] + b0, c[i][j][3] + b1);
                    }
                }
            }
        }
    }
}

// ---------------- RMSNorm over full C per row (fp32 in -> fp16 out, scale folded) ----------------
__global__ void rmsnorm_kernel(const float* __restrict__ qin, const float* __restrict__ kin,
                               __half* __restrict__ qout, __half* __restrict__ kout,
                               const float* __restrict__ qw, const float* __restrict__ kw)
{
    const float* in = blockIdx.y ? kin : qin;
    __half* outp    = blockIdx.y ? kout : qout;
    const float* w  = blockIdx.y ? kw : qw;
    const float post = blockIdx.y ? 1.f : 0.08838834764831845f;   // q: fold attn scale
    const size_t row = blockIdx.x;
    const float4* p  = (const float4*)(in + row * CH);
    const float4* wp = (const float4*)w;

    const int tid = threadIdx.x;
    float ss = 0.f;
    for (int i = tid; i < CH / 4; i += 256) {
        float4 v = p[i];
        ss += v.x * v.x + v.y * v.y + v.z * v.z + v.w * v.w;
    }
    __shared__ float red[8];
    #pragma unroll
    for (int off = 16; off > 0; off >>= 1) ss += __shfl_xor_sync(0xffffffffu, ss, off);
    if ((tid & 31) == 0) red[tid >> 5] = ss;
    __syncthreads();
    float tot = 0.f;
    #pragma unroll
    for (int i = 0; i < 8; i++) tot += red[i];
    const float rms = rsqrtf(tot * (1.f / CH) + EPS) * post;

    __half2* op = (__half2*)(outp + row * CH);
    for (int i = tid; i < CH / 4; i += 256) {
        float4 v = p[i];
        float4 wv = wp[i];
        op[2 * i]     = __floats2half2_rn(v.x * rms * wv.x, v.y * rms * wv.y);
        op[2 * i + 1] = __floats2half2_rn(v.z * rms * wv.z, v.w * rms * wv.w);
    }
}

// ---------------- flash attention, fp16 mma, register-resident P ----------------
#define ROWB 272
#define AQ_BYTES (128*ROWB)
#define KV_BYTES (2*64*ROWB)
#define ATTN_SMEM (AQ_BYTES + 2*KV_BYTES)  // 104448

__global__ void __launch_bounds__(256, 2) attn_kernel(
    const __half* __restrict__ Q, const __half* __restrict__ K,
    const __half* __restrict__ V, __half* __restrict__ O)
{
    extern __shared__ char smg[];
    const uint32_t sb = smem_u32(smg);
    const int tid  = threadIdx.x;
    const int lane = tid & 31;
    const int wid  = tid >> 5;
    const int g    = lane >> 2;
    const int q    = lane & 3;
    const int bh   = blockIdx.x;
    const int b    = bh / NH;
    const int h    = bh % NH;
    const int q0   = blockIdx.y * 128;
    const size_t rowBase = (size_t)b * SEQ;
    const int nkt = (SEQ + 63) / 64;     // 17

    for (int i = tid; i < 2048; i += 256) {
        int r = i >> 4, c = i & 15;
        int grow = q0 + r;
        const __half* src = Q + (rowBase + grow) * (size_t)CH + h * HD + c * 8;
        cp_async16(sb + r * ROWB + c * 16, src, grow < SEQ ? 16 : 0);
    }
    cp_commit();

    auto kvstage = [&](int kt) {
        const int k0 = kt * 64;
        const uint32_t bufb = sb + AQ_BYTES + (kt & 1) * KV_BYTES;
        for (int i = tid; i < 1024; i += 256) {
            int r = i >> 4, c = i & 15;
            int krow = k0 + r;
            size_t off = (rowBase + krow) * (size_t)CH + h * HD + c * 8;
            int ok = krow < SEQ ? 16 : 0;
            cp_async16(bufb + r * ROWB + c * 16, K + off, ok);
            cp_async16(bufb + 64 * ROWB + r * ROWB + c * 16, V + off, ok);
        }
        cp_commit();
    };

    kvstage(0);

    if (tid < 128) {
        int buf = tid >> 6, r = tid & 63;
        uint4* p = (uint4*)(smg + AQ_BYTES + buf * KV_BYTES + 64 * ROWB + r * ROWB + 256);
        *p = make_uint4(0x00003c00u, 0u, 0u, 0u);   // halves {1,0,0,0,0,0,0,0}
    }

    float o[17][4];
    #pragma unroll
    for (int j = 0; j < 17; j++)
        #pragma unroll
        for (int t = 0; t < 4; t++) o[j][t] = 0.f;
    float mstat0 = -1e30f, mstat1 = -1e30f;

    const uint32_t aQbase = sb + (wid * 16 + (lane & 15)) * ROWB + ((lane >> 4) << 4);
    const int bRowOff = (lane & 7) + ((lane & 16) >> 1);
    const int bKb     = (lane & 8) << 1;
    const int vRowOff = ((lane >> 3) & 1) * 8 + (lane & 7);
    const int vColOff = (lane >> 4) << 4;

    for (int kt = 0; kt < nkt; kt++) {
        if (kt + 1 < nkt) kvstage(kt + 1);
        else cp_commit();
        cp_wait1();
        __syncthreads();

        const uint32_t Kb = sb + AQ_BYTES + (kt & 1) * KV_BYTES;
        const uint32_t Vb = Kb + 64 * ROWB;

        float s[8][4];
        #pragma unroll
        for (int nt = 0; nt < 8; nt++)
            #pragma unroll
            for (int t = 0; t < 4; t++) s[nt][t] = 0.f;
        #pragma unroll
        for (int kb = 0; kb < 8; kb++) {
            uint32_t a[4];
            ldsm_x4(a, aQbase + kb * 32);
            #pragma unroll
            for (int nt = 0; nt < 4; nt++) {
                uint32_t bf[4];
                ldsm_x4(bf, Kb + (nt * 16 + bRowOff) * ROWB + kb * 32 + bKb);
                mma16816(s[2 * nt],     a, bf[0], bf[1]);
                mma16816(s[2 * nt + 1], a, bf[2], bf[3]);
            }
        }

        const int kvalid = SEQ - kt * 64;
        if (kvalid < 64) {
            #pragma unroll
            for (int nt = 0; nt < 8; nt++) {
                int colb = nt * 8 + 2 * q;
                if (colb >= kvalid)     { s[nt][0] = -1e30f; s[nt][2] = -1e30f; }
                if (colb + 1 >= kvalid) { s[nt][1] = -1e30f; s[nt][3] = -1e30f; }
            }
        }

        float cm0 = -1e30f, cm1 = -1e30f;
        #pragma unroll
        for (int nt = 0; nt < 8; nt++) {
            cm0 = fmaxf(cm0, fmaxf(s[nt][0], s[nt][1]));
            cm1 = fmaxf(cm1, fmaxf(s[nt][2], s[nt][3]));
        }
        cm0 = fmaxf(cm0, __shfl_xor_sync(0xffffffffu, cm0, 1));
        cm0 = fmaxf(cm0, __shfl_xor_sync(0xffffffffu, cm0, 2));
        cm1 = fmaxf(cm1, __shfl_xor_sync(0xffffffffu, cm1, 1));
        cm1 = fmaxf(cm1, __shfl_xor_sync(0xffffffffu, cm1, 2));

        const float mn0 = fmaxf(mstat0, cm0);
        const float mn1 = fmaxf(mstat1, cm1);
        const float al0 = __expf(mstat0 - mn0);
        const float al1 = __expf(mstat1 - mn1);
        mstat0 = mn0; mstat1 = mn1;
        const float cc0 = -mn0 * LOG2E;
        const float cc1 = -mn1 * LOG2E;

        uint32_t ph[8][2];
        #pragma unroll
        for (int nt = 0; nt < 8; nt++) {
            ph[nt][0] = ex2_h2(pack_h2(fmaf(s[nt][0], LOG2E, cc0),
                                       fmaf(s[nt][1], LOG2E, cc0)));
            ph[nt][1] = ex2_h2(pack_h2(fmaf(s[nt][2], LOG2E, cc1),
                                       fmaf(s[nt][3], LOG2E, cc1)));
        }

        if (__float_as_uint(al0) != 0x3f800000u || __float_as_uint(al1) != 0x3f800000u) {
            #pragma unroll
            for (int j = 0; j < 17; j++) {
                o[j][0] *= al0; o[j][1] *= al0;
                o[j][2] *= al1; o[j][3] *= al1;
            }
        }

        #pragma unroll
        for (int m = 0; m < 4; m++) {
            uint32_t a[4] = { ph[2 * m][0], ph[2 * m][1], ph[2 * m + 1][0], ph[2 * m + 1][1] };
            const uint32_t vb = Vb + (m * 16 + vRowOff) * ROWB;
            #pragma unroll
            for (int nb = 0; nb < 8; nb++) {
                uint32_t r[4];
                ldsm_x4t(r, vb + nb * 32 + vColOff);
                mma16816(o[2 * nb],     a, r[0], r[1]);
                mma16816(o[2 * nb + 1], a, r[2], r[3]);
            }
            uint32_t rl[2];
            ldsm_x2t(rl, Vb + (m * 16 + vRowOff) * ROWB + 256);
            mma16816(o[16], a, rl[0], rl[1]);
        }
        __syncthreads();
    }

    const float l0 = __shfl_sync(0xffffffffu, o[16][0], lane & ~3);
    const float l1 = __shfl_sync(0xffffffffu, o[16][2], lane & ~3);
    const float inv0 = 1.f / l0;
    const float inv1 = 1.f / l1;
    const int row0 = q0 + wid * 16 + g;
    #pragma unroll
    for (int j = 0; j < 16; j++) {
        int col = h * HD + j * 8 + 2 * q;
        if (row0 < SEQ) {
            __half2* d = (__half2*)(O + (rowBase + row0) * (size_t)CH + col);
            *d = __floats2half2_rn(o[j][0] * inv0, o[j][1] * inv0);
        }
        if (row0 + 8 < SEQ) {
            __half2* d = (__half2*)(O + (rowBase + row0 + 8) * (size_t)CH + col);
            *d = __floats2half2_rn(o[j][2] * inv1, o[j][3] * inv1);
        }
    }
}

// ---------------- launch ----------------
extern "C" void kernel_launch(void* const* d_in, const int* in_sizes, int n_in,
                              void* d_out, int out_size)
{
    const float* x     = (const float*)d_in[0];
    const float* qkvW  = (const float*)d_in[1];
    const float* qkvB  = (const float*)d_in[2];
    const float* qNW   = (const float*)d_in[3];
    const float* kNW   = (const float*)d_in[4];
    const float* projW = (const float*)d_in[5];
    const float* projB = (const float*)d_in[6];
    float* out = (float*)d_out;

    __half *pxh, *pwqT, *pwpT, *pqh, *pkh, *pvh, *po;
    float *pq, *pk;
    cudaGetSymbolAddress((void**)&pxh,  g_xh);
    cudaGetSymbolAddress((void**)&pwqT, g_wqkvT);
    cudaGetSymbolAddress((void**)&pwpT, g_wprojT);
    cudaGetSymbolAddress((void**)&pq,   g_q);
    cudaGetSymbolAddress((void**)&pk,   g_k);
    cudaGetSymbolAddress((void**)&pqh,  g_qh);
    cudaGetSymbolAddress((void**)&pkh,  g_kh);
    cudaGetSymbolAddress((void**)&pvh,  g_vh);
    cudaGetSymbolAddress((void**)&po,   g_o);

    cudaFuncSetAttribute(hgemm,       cudaFuncAttributeMaxDynamicSharedMemorySize, HG_SMEM);
    cudaFuncSetAttribute(attn_kernel, cudaFuncAttributeMaxDynamicSharedMemorySize, ATTN_SMEM);

    const int n1 = MROWS * CH;
    f2h_kernel<<<(n1 / 4 + 255) / 256, 256>>>((const float4*)x, (uint2*)pxh, n1 / 4);
    transpose_h<<<dim3(3 * CH / 32, CH / 32), dim3(32, 8)>>>(qkvW, pwqT, CH, 3 * CH);
    transpose_h<<<dim3(CH / 32, CH / 32), dim3(32, 8)>>>(projW, pwpT, CH, CH);

    // qkv = x @ W_qkv + b  ->  q(f32), k(f32), v(f16)
    hgemm<<<dim3(65, 75), 128, HG_SMEM>>>(pxh, pwqT, qkvB, pq, pk, pvh, nullptr, MROWS, 1);
    // RMSNorm (q gets attn scale folded) -> fp16
    rmsnorm_kernel<<<dim3(MROWS, 2), 256>>>(pq, pk, pqh, pkh, qNW, kNW);
    // flash attention (fp16 tensor cores) -> fp16
    attn_kernel<<<dim3(BATCH * NH, (SEQ + 127) / 128), 256, ATTN_SMEM>>>(pqh, pkh, pvh, po);
    // out = attn_out @ W_proj + b (fp32 out)
    hgemm<<<dim3(65, 25), 128, HG_SMEM>>>(po, pwpT, projB, nullptr, nullptr, nullptr, out, MROWS, 0);
}